// round 11
// baseline (speedup 1.0000x reference)
#include <cuda_runtime.h>
#include <cuda_bf16.h>
#include <math.h>
#include <stdint.h>

#define BATCH 2
#define SEQ   2048
#define DMODEL 4096
#define NHEADS 32
#define NKVH  8
#define HEADD 128
#define KVLEN 2048

// QSCALE * log2(e): softmax done in base-2
#define QSC2 (0.08838834764831845f * 1.4426950408889634f)

// ---------------------------------------------------------------------------
// Global scratch
// ---------------------------------------------------------------------------
#define PLANE_U32 (8388608)
__device__ uint32_t g_xhi[PLANE_U32],  g_xlo[PLANE_U32];   // x rows (b*s, k)
__device__ uint32_t g_wqhi[PLANE_U32], g_wqlo[PLANE_U32];  // wq (n, k)
__device__ uint32_t g_wohi[PLANE_U32], g_wolo[PLANE_U32];  // wo (n, k)
__device__ uint32_t g_qhi[PLANE_U32],  g_qlo[PLANE_U32];   // q (b,h,s,d)
__device__ uint32_t g_ahi[PLANE_U32],  g_alo[PLANE_U32];   // attn out (b*s, h*d)
#define KV_U32 (2097152)
__device__ uint32_t g_khi[KV_U32], g_klo[KV_U32];          // (b,g,s,d)
__device__ uint32_t g_vhi[KV_U32], g_vlo[KV_U32];
// split-K fp32 partials (2 x 64MB)
__device__ float g_p0[16777216], g_p1[16777216];

// ---------------------------------------------------------------------------
__device__ __forceinline__ uint32_t smem_to_u32(const void* p) {
    uint32_t a;
    asm("{ .reg .u64 t; cvta.to.shared.u64 t, %1; cvt.u32.u64 %0, t; }" : "=r"(a) : "l"(p));
    return a;
}
#define SWZ64(off)  ((uint32_t)(off) ^ ((((uint32_t)(off)) >> 3) & 0x30u))
#define SWZ256(off) ((uint32_t)(off) ^ ((((uint32_t)(off)) >> 4) & 0x70u))

__device__ __forceinline__ void cp16(uint32_t dst, const void* src) {
    asm volatile("cp.async.cg.shared.global [%0], [%1], 16;" :: "r"(dst), "l"(src));
}
#define CP_COMMIT asm volatile("cp.async.commit_group;" ::: "memory")
#define CP_WAIT(n) asm volatile("cp.async.wait_group %0;" :: "n"(n) : "memory")

__device__ __forceinline__ void ldsm_x4(uint32_t& r0, uint32_t& r1, uint32_t& r2, uint32_t& r3,
                                        uint32_t addr) {
    asm volatile("ldmatrix.sync.aligned.m8n8.x4.shared.b16 {%0,%1,%2,%3}, [%4];"
                 : "=r"(r0), "=r"(r1), "=r"(r2), "=r"(r3) : "r"(addr));
}
__device__ __forceinline__ void ldsm_x4_t(uint32_t& r0, uint32_t& r1, uint32_t& r2, uint32_t& r3,
                                          uint32_t addr) {
    asm volatile("ldmatrix.sync.aligned.m8n8.x4.trans.shared.b16 {%0,%1,%2,%3}, [%4];"
                 : "=r"(r0), "=r"(r1), "=r"(r2), "=r"(r3) : "r"(addr));
}
__device__ __forceinline__ void mma_bf16(float* d, const uint32_t* a, uint32_t b0, uint32_t b1) {
    asm volatile(
        "mma.sync.aligned.m16n8k16.row.col.f32.bf16.bf16.f32 "
        "{%0,%1,%2,%3}, {%4,%5,%6,%7}, {%8,%9}, {%0,%1,%2,%3};"
        : "+f"(d[0]), "+f"(d[1]), "+f"(d[2]), "+f"(d[3])
        : "r"(a[0]), "r"(a[1]), "r"(a[2]), "r"(a[3]), "r"(b0), "r"(b1));
}
__device__ __forceinline__ void pack_hilo(float a, float b, uint32_t& hi, uint32_t& lo) {
    uint32_t h;
    asm("cvt.rn.bf16x2.f32 %0, %1, %2;" : "=r"(h) : "f"(b), "f"(a));
    float fa = __uint_as_float(h << 16);
    float fb = __uint_as_float(h & 0xffff0000u);
    float ra = a - fa;
    float rb = b - fb;
    uint32_t l;
    asm("cvt.rn.bf16x2.f32 %0, %1, %2;" : "=r"(l) : "f"(rb), "f"(ra));
    hi = h; lo = l;
}

// ---------------------------------------------------------------------------
// Conversion kernels
// ---------------------------------------------------------------------------
__global__ void conv3(const float4* __restrict__ s0, const float4* __restrict__ s1,
                      const float4* __restrict__ s2,
                      uint2* h0, uint2* l0, uint2* h1, uint2* l1, uint2* h2, uint2* l2)
{
    const float4* src = (blockIdx.y == 0) ? s0 : (blockIdx.y == 1) ? s1 : s2;
    uint2* hi = (blockIdx.y == 0) ? h0 : (blockIdx.y == 1) ? h1 : h2;
    uint2* lo = (blockIdx.y == 0) ? l0 : (blockIdx.y == 1) ? l1 : l2;
    const int n4 = PLANE_U32 / 2;
    for (int i = blockIdx.x * blockDim.x + threadIdx.x; i < n4;
         i += gridDim.x * blockDim.x) {
        float4 v = src[i];
        uint32_t ha, la, hb, lb;
        pack_hilo(v.x, v.y, ha, la);
        pack_hilo(v.z, v.w, hb, lb);
        hi[i] = make_uint2(ha, hb);
        lo[i] = make_uint2(la, lb);
    }
}

__global__ void conv_kv4(const float4* __restrict__ ksrc, const float4* __restrict__ vsrc,
                         uint2* kh, uint2* kl, uint2* vh, uint2* vl)
{
    const float4* src = blockIdx.y ? vsrc : ksrc;
    uint2* hi = blockIdx.y ? vh : kh;
    uint2* lo = blockIdx.y ? vl : kl;
    const int n4 = KV_U32 / 2;
    for (int p = blockIdx.x * blockDim.x + threadIdx.x; p < n4;
         p += gridDim.x * blockDim.x) {
        const int d4 = p & 31;
        const int s = (p >> 5) & 2047;
        const int g = (p >> 16) & 7;
        const int b = p >> 19;
        float4 v = src[(((size_t)b * SEQ + s) * NKVH + g) * 32 + d4];
        uint32_t ha, la, hb, lb;
        pack_hilo(v.x, v.y, ha, la);
        pack_hilo(v.z, v.w, hb, lb);
        hi[p] = make_uint2(ha, hb);
        lo[p] = make_uint2(la, lb);
    }
}

// ---------------------------------------------------------------------------
// Split-K bf16-split GEMM: P[z] = A[:, zK/2:(z+1)K/2] @ B^T (half-K partial).
// 3 passes. CTA 128x128, 8 warps (32x64 each), K-chunk 32,
// 3-stage cp.async (32KB stages, SW64), 2 CTAs/SM. Grid (32,32,2).
// ---------------------------------------------------------------------------
#define GEMM_SMEM (3 * 32768)

__global__ __launch_bounds__(256, 2) void gemm_bf16_sk(
    const uint32_t* __restrict__ Ahi, const uint32_t* __restrict__ Alo,
    const uint32_t* __restrict__ Bhi, const uint32_t* __restrict__ Blo,
    float* __restrict__ P0, float* __restrict__ P1)
{
    extern __shared__ char sm[];
    const uint32_t smb = smem_to_u32(sm);
    const int tid = threadIdx.x;
    const int wid = tid >> 5;
    const int lane = tid & 31;
    const int wn = wid & 1;          // n half (64)
    const int wm = wid >> 1;         // m quarter (32)
    const int m0 = blockIdx.y * 128;
    const int n0 = blockIdx.x * 128;
    const int kz = blockIdx.z * 1024;   // u32 col base of this K half
    float* __restrict__ P = blockIdx.z ? P1 : P0;

    float acc[2][8][4];
#pragma unroll
    for (int i = 0; i < 2; i++)
#pragma unroll
        for (int j = 0; j < 8; j++)
#pragma unroll
            for (int v = 0; v < 4; v++) acc[i][j][v] = 0.0f;

    auto load_stage = [&](int ch, int st) {
        const uint32_t sbase = smb + (uint32_t)st * 32768u;
        const int kc2 = kz + ch * 16;
#pragma unroll
        for (int t = tid; t < 2048; t += 256) {
            const int plane = t >> 9;            // Ahi Alo Bhi Blo
            const int i = t & 511;
            const int row = i >> 2, ck = i & 3;
            const uint32_t dst = sbase + plane * 8192u + SWZ64(row * 64 + ck * 16);
            const uint32_t* bp = (plane == 0) ? Ahi : (plane == 1) ? Alo
                                : (plane == 2) ? Bhi : Blo;
            const int r0 = (plane < 2) ? m0 : n0;
            cp16(dst, bp + (size_t)(r0 + row) * 2048 + kc2 + ck * 4);
        }
    };

    const int q = lane >> 3;
    const int wi = lane & 7;
    const int arow_base = wm * 32 + wi + ((q & 1) ? 8 : 0);
    const int akb_off = (q & 2) ? 16 : 0;
    const int brow_base = wn * 64 + wi + ((q & 2) ? 8 : 0);
    const int bkb_off = (q & 1) ? 16 : 0;

    load_stage(0, 0); CP_COMMIT;
    load_stage(1, 1); CP_COMMIT;

    for (int ch = 0; ch < 64; ++ch) {
        if (ch < 63) CP_WAIT(1); else CP_WAIT(0);
        __syncthreads();
        if (ch + 2 < 64) { load_stage(ch + 2, (ch + 2) % 3); CP_COMMIT; }

        const uint32_t sbase = smb + (uint32_t)(ch % 3) * 32768u;
        const uint32_t pAhi = sbase,           pAlo = sbase + 8192u;
        const uint32_t pBhi = sbase + 16384u,  pBlo = sbase + 24576u;

#pragma unroll
        for (int ks = 0; ks < 2; ++ks) {
            const int kb0 = ks * 32;
            uint32_t ah[2][4], al[2][4];
#pragma unroll
            for (int mt = 0; mt < 2; ++mt) {
                const int r = arow_base + mt * 16;
                const uint32_t off = SWZ64(r * 64 + kb0 + akb_off);
                ldsm_x4(ah[mt][0], ah[mt][1], ah[mt][2], ah[mt][3], pAhi + off);
                ldsm_x4(al[mt][0], al[mt][1], al[mt][2], al[mt][3], pAlo + off);
            }
#pragma unroll
            for (int np = 0; np < 4; ++np) {
                const int rn = brow_base + np * 16;
                const uint32_t offb = SWZ64(rn * 64 + kb0 + bkb_off);
                uint32_t bh[4], bl[4];
                ldsm_x4(bh[0], bh[1], bh[2], bh[3], pBhi + offb);
                ldsm_x4(bl[0], bl[1], bl[2], bl[3], pBlo + offb);
#pragma unroll
                for (int mt = 0; mt < 2; ++mt) {
                    mma_bf16(acc[mt][np * 2],     ah[mt], bh[0], bh[1]);
                    mma_bf16(acc[mt][np * 2 + 1], ah[mt], bh[2], bh[3]);
                    mma_bf16(acc[mt][np * 2],     ah[mt], bl[0], bl[1]);
                    mma_bf16(acc[mt][np * 2 + 1], ah[mt], bl[2], bl[3]);
                    mma_bf16(acc[mt][np * 2],     al[mt], bh[0], bh[1]);
                    mma_bf16(acc[mt][np * 2 + 1], al[mt], bh[2], bh[3]);
                }
            }
        }
    }

    // epilogue: plain fp32 partial store
    const int rl = lane >> 2;
    const int cl = (lane & 3) * 2;
#pragma unroll
    for (int mt = 0; mt < 2; ++mt) {
#pragma unroll
        for (int nn = 0; nn < 8; ++nn) {
            const int r = m0 + wm * 32 + mt * 16 + rl;
            const int c = n0 + wn * 64 + nn * 8 + cl;
#pragma unroll
            for (int half = 0; half < 2; ++half) {
                const int rr = r + half * 8;
                *(float2*)&P[(size_t)rr * DMODEL + c] =
                    make_float2(acc[mt][nn][half * 2], acc[mt][nn][half * 2 + 1]);
            }
        }
    }
}

// ---------------------------------------------------------------------------
// Split-K reduction kernels (fused epilogues). 4 floats per thread.
// ---------------------------------------------------------------------------
__global__ void reduce_plain(const float4* __restrict__ p0, const float4* __restrict__ p1,
                             float4* __restrict__ out)
{
    const int i = blockIdx.x * blockDim.x + threadIdx.x;   // 4.19M exactly
    float4 a = p0[i], b = p1[i];
    out[i] = make_float4(a.x + b.x, a.y + b.y, a.z + b.z, a.w + b.w);
}

__global__ void reduce_qproj(const float4* __restrict__ p0, const float4* __restrict__ p1,
                             const float* __restrict__ freqs,
                             uint32_t* __restrict__ Qh, uint32_t* __restrict__ Ql)
{
    const int i = blockIdx.x * blockDim.x + threadIdx.x;
    const int o = i << 2;
    const int row = o >> 12;          // / 4096
    const int col = o & 4095;
    const int b = row >> 11;
    const int s = row & (SEQ - 1);
    const int h = col >> 7;
    const int d = col & (HEADD - 1);
    float4 f = *(const float4*)&freqs[(size_t)s * 64 + (d & 63)];
    float4 a = p0[i], c = p1[i];
    const float v0 = (a.x + c.x) * f.x * QSC2;
    const float v1 = (a.y + c.y) * f.y * QSC2;
    const float v2 = (a.z + c.z) * f.z * QSC2;
    const float v3 = (a.w + c.w) * f.w * QSC2;
    uint32_t h0, l0, h1, l1;
    pack_hilo(v0, v1, h0, l0);
    pack_hilo(v2, v3, h1, l1);
    const size_t idx = (((size_t)b * NHEADS + h) * SEQ + s) * 64 + (d >> 1);
    *(uint2*)&Qh[idx] = make_uint2(h0, h1);
    *(uint2*)&Ql[idx] = make_uint2(l0, l1);
}

// ---------------------------------------------------------------------------
// Tensor-core flash attention (causal), bf16 hi/lo 3-pass, base-2 softmax.
// CTA: 64 q-rows x one (b,h), 4 warps x 16 rows, KV blocks of 32.
// 3-stage cp.async (32KB stages), Q staged through region 0, 2 CTAs/SM.
// ---------------------------------------------------------------------------
#define ATT_SMEM (3 * 32768)

__global__ __launch_bounds__(128, 2) void attn_tc(
    const uint32_t* __restrict__ Qhi, const uint32_t* __restrict__ Qlo,
    const uint32_t* __restrict__ Khi, const uint32_t* __restrict__ Klo,
    const uint32_t* __restrict__ Vhi, const uint32_t* __restrict__ Vlo,
    uint32_t* __restrict__ Ohi, uint32_t* __restrict__ Olo)
{
    extern __shared__ char sm[];
    const uint32_t smb = smem_to_u32(sm);
    const int tid = threadIdx.x;
    const int w = tid >> 5;
    const int lane = tid & 31;
    const int bx = gridDim.x - 1 - blockIdx.x;   // big tiles first
    const int by = blockIdx.y;
    const int b = by >> 5, h = by & 31, g = h >> 2;
    const int q0 = bx * 64;
    const int nb = 2 * bx + 2;                   // KV blocks of 32 rows

    // --- Q load (64 rows x 2 planes = 32KB) into region 0 ---
    const size_t qbase = (((size_t)b * NHEADS + h) * SEQ + q0) * 64;
#pragma unroll
    for (int t = tid; t < 2048; t += 128) {
        const int plane = t >> 10;
        const int i = t & 1023;
        const int row = i >> 4, ck = i & 15;
        const uint32_t dst = smb + plane * 16384u + SWZ256(row * 256 + ck * 16);
        cp16(dst, (plane ? Qlo : Qhi) + qbase + (size_t)row * 64 + ck * 4);
    }
    CP_COMMIT;

    const size_t kvbase = ((size_t)b * NKVH + g) * KVLEN * 64;
    auto load_kv = [&](int jb, int region) {
        const uint32_t sb = smb + (uint32_t)region * 32768u;
        const int kv0 = jb * 32;
#pragma unroll
        for (int t = tid; t < 2048; t += 128) {
            const int plane = t >> 9;                 // Khi Klo Vhi Vlo
            const int i = t & 511;
            const int row = i >> 4, ck = i & 15;
            const uint32_t dst = sb + plane * 8192u + SWZ256(row * 256 + ck * 16);
            const uint32_t* base = (plane < 2) ? (plane & 1 ? Klo : Khi)
                                               : (plane & 1 ? Vlo : Vhi);
            cp16(dst, base + kvbase + (size_t)(kv0 + row) * 64 + ck * 4);
        }
    };

    load_kv(0, 1); CP_COMMIT;
    load_kv(1, 2); CP_COMMIT;
    CP_WAIT(2);                 // Q done
    __syncthreads();

    // --- preload Q fragments from region 0 (then region 0 becomes a stage) ---
    const int wi = lane & 7, qq = lane >> 3;
    const int arow = w * 16 + wi + ((qq & 1) ? 8 : 0);
    const int akoff = (qq & 2) ? 16 : 0;
    uint32_t qh[8][4], ql[8][4];
#pragma unroll
    for (int ks = 0; ks < 8; ks++) {
        const uint32_t off = SWZ256(arow * 256 + ks * 32 + akoff);
        ldsm_x4(qh[ks][0], qh[ks][1], qh[ks][2], qh[ks][3], smb + off);
        ldsm_x4(ql[ks][0], ql[ks][1], ql[ks][2], ql[ks][3], smb + 16384u + off);
    }
    __syncthreads();            // all warps done with region 0 before refill

    float oacc[16][4];
#pragma unroll
    for (int i = 0; i < 16; i++)
#pragma unroll
        for (int v = 0; v < 4; v++) oacc[i][v] = 0.0f;
    float mprev0 = -INFINITY, mprev1 = -INFINITY;
    float lsum0 = 0.0f, lsum1 = 0.0f;

    const int rl = lane >> 2, cl2 = (lane & 3) * 2;
    const int row0g = q0 + w * 16 + rl;
    const int row1g = row0g + 8;
    const int brow = wi + ((qq & 2) ? 8 : 0);
    const int bkoff = (qq & 1) ? 16 : 0;
    const int vkr = (lane & 7) + ((lane & 8) ? 8 : 0);
    const int vnoff = (lane & 16) ? 16 : 0;

    for (int jb = 0; jb < nb; ++jb) {
        if (jb < nb - 1) CP_WAIT(1); else CP_WAIT(0);
        __syncthreads();
        if (jb + 2 < nb) { load_kv(jb + 2, jb % 3); CP_COMMIT; }
        const uint32_t sb = smb + (uint32_t)((jb + 1) % 3) * 32768u;

        // --- S = Q @ K^T (3-pass), scores in log2 domain ---
        float sacc[4][4];
#pragma unroll
        for (int i = 0; i < 4; i++)
#pragma unroll
            for (int v = 0; v < 4; v++) sacc[i][v] = 0.0f;
#pragma unroll
        for (int ks = 0; ks < 8; ks++) {
#pragma unroll
            for (int nt2 = 0; nt2 < 2; nt2++) {
                const uint32_t off = SWZ256((nt2 * 16 + brow) * 256 + ks * 32 + bkoff);
                uint32_t bh[4], bl[4];
                ldsm_x4(bh[0], bh[1], bh[2], bh[3], sb + off);
                ldsm_x4(bl[0], bl[1], bl[2], bl[3], sb + 8192u + off);
                mma_bf16(sacc[nt2 * 2],     qh[ks], bh[0], bh[1]);
                mma_bf16(sacc[nt2 * 2 + 1], qh[ks], bh[2], bh[3]);
                mma_bf16(sacc[nt2 * 2],     qh[ks], bl[0], bl[1]);
                mma_bf16(sacc[nt2 * 2 + 1], qh[ks], bl[2], bl[3]);
                mma_bf16(sacc[nt2 * 2],     ql[ks], bh[0], bh[1]);
                mma_bf16(sacc[nt2 * 2 + 1], ql[ks], bh[2], bh[3]);
            }
        }

        // --- causal mask ---
        if (jb >= 2 * bx) {
            const int kv0 = jb * 32;
#pragma unroll
            for (int nt = 0; nt < 4; nt++) {
                const int c0 = kv0 + nt * 8 + cl2;
                const int c1 = c0 + 1;
                if (c0 > row0g) sacc[nt][0] = -1e30f;
                if (c1 > row0g) sacc[nt][1] = -1e30f;
                if (c0 > row1g) sacc[nt][2] = -1e30f;
                if (c1 > row1g) sacc[nt][3] = -1e30f;
            }
        }

        // --- online softmax (base 2) ---
        float mx0 = -1e30f, mx1 = -1e30f;
#pragma unroll
        for (int nt = 0; nt < 4; nt++) {
            mx0 = fmaxf(mx0, fmaxf(sacc[nt][0], sacc[nt][1]));
            mx1 = fmaxf(mx1, fmaxf(sacc[nt][2], sacc[nt][3]));
        }
        mx0 = fmaxf(mx0, __shfl_xor_sync(0xffffffffu, mx0, 1));
        mx0 = fmaxf(mx0, __shfl_xor_sync(0xffffffffu, mx0, 2));
        mx1 = fmaxf(mx1, __shfl_xor_sync(0xffffffffu, mx1, 1));
        mx1 = fmaxf(mx1, __shfl_xor_sync(0xffffffffu, mx1, 2));
        const float mnew0 = fmaxf(mprev0, mx0);
        const float mnew1 = fmaxf(mprev1, mx1);
        const float alpha0 = exp2f(mprev0 - mnew0);
        const float alpha1 = exp2f(mprev1 - mnew1);
        float rs0 = 0.0f, rs1 = 0.0f;
#pragma unroll
        for (int nt = 0; nt < 4; nt++) {
            sacc[nt][0] = exp2f(sacc[nt][0] - mnew0);
            sacc[nt][1] = exp2f(sacc[nt][1] - mnew0);
            sacc[nt][2] = exp2f(sacc[nt][2] - mnew1);
            sacc[nt][3] = exp2f(sacc[nt][3] - mnew1);
            rs0 += sacc[nt][0] + sacc[nt][1];
            rs1 += sacc[nt][2] + sacc[nt][3];
        }
        rs0 += __shfl_xor_sync(0xffffffffu, rs0, 1);
        rs0 += __shfl_xor_sync(0xffffffffu, rs0, 2);
        rs1 += __shfl_xor_sync(0xffffffffu, rs1, 1);
        rs1 += __shfl_xor_sync(0xffffffffu, rs1, 2);
        lsum0 = lsum0 * alpha0 + rs0;
        lsum1 = lsum1 * alpha1 + rs1;
#pragma unroll
        for (int nt = 0; nt < 16; nt++) {
            oacc[nt][0] *= alpha0; oacc[nt][1] *= alpha0;
            oacc[nt][2] *= alpha1; oacc[nt][3] *= alpha1;
        }
        mprev0 = mnew0; mprev1 = mnew1;

        // --- O += P @ V (3-pass) ---
#pragma unroll
        for (int jp = 0; jp < 2; jp++) {
            uint32_t pah[4], pal[4];
            pack_hilo(sacc[2 * jp][0],     sacc[2 * jp][1],     pah[0], pal[0]);
            pack_hilo(sacc[2 * jp][2],     sacc[2 * jp][3],     pah[1], pal[1]);
            pack_hilo(sacc[2 * jp + 1][0], sacc[2 * jp + 1][1], pah[2], pal[2]);
            pack_hilo(sacc[2 * jp + 1][2], sacc[2 * jp + 1][3], pah[3], pal[3]);
#pragma unroll
            for (int nt2 = 0; nt2 < 8; nt2++) {
                const uint32_t off = SWZ256((jp * 16 + vkr) * 256 + nt2 * 32 + vnoff);
                uint32_t vh[4], vl[4];
                ldsm_x4_t(vh[0], vh[1], vh[2], vh[3], sb + 16384u + off);
                ldsm_x4_t(vl[0], vl[1], vl[2], vl[3], sb + 24576u + off);
                mma_bf16(oacc[nt2 * 2],     pah, vh[0], vh[1]);
                mma_bf16(oacc[nt2 * 2 + 1], pah, vh[2], vh[3]);
                mma_bf16(oacc[nt2 * 2],     pal, vh[0], vh[1]);
                mma_bf16(oacc[nt2 * 2 + 1], pal, vh[2], vh[3]);
                mma_bf16(oacc[nt2 * 2],     pah, vl[0], vl[1]);
                mma_bf16(oacc[nt2 * 2 + 1], pah, vl[2], vl[3]);
            }
        }
    }

    // --- epilogue ---
    const float inv0 = 1.0f / lsum0;
    const float inv1 = 1.0f / lsum1;
    const size_t r0 = ((size_t)b * SEQ + row0g) * 2048 + h * 64;
    const size_t r1 = ((size_t)b * SEQ + row1g) * 2048 + h * 64;
#pragma unroll
    for (int nt = 0; nt < 16; nt++) {
        const int d2 = (nt * 8 + cl2) >> 1;
        uint32_t hi0, lo0, hi1, lo1;
        pack_hilo(oacc[nt][0] * inv0, oacc[nt][1] * inv0, hi0, lo0);
        pack_hilo(oacc[nt][2] * inv1, oacc[nt][3] * inv1, hi1, lo1);
        Ohi[r0 + d2] = hi0; Olo[r0 + d2] = lo0;
        Ohi[r1 + d2] = hi1; Olo[r1 + d2] = lo1;
    }
}

// ---------------------------------------------------------------------------
extern "C" void kernel_launch(void* const* d_in, const int* in_sizes, int n_in,
                              void* d_out, int out_size)
{
    (void)in_sizes; (void)n_in; (void)out_size;
    const float* x     = (const float*)d_in[0];
    const float* freqs = (const float*)d_in[1];
    const float* wq    = (const float*)d_in[3];
    const float* wo    = (const float*)d_in[6];
    const float* ck    = (const float*)d_in[7];
    const float* cv    = (const float*)d_in[8];
    float* out = (float*)d_out;

    void *xhi, *xlo, *wqhi, *wqlo, *wohi, *wolo, *qhi, *qlo, *ahi, *alo;
    void *khi, *klo, *vhi, *vlo, *p0, *p1;
    cudaGetSymbolAddress(&xhi, g_xhi);   cudaGetSymbolAddress(&xlo, g_xlo);
    cudaGetSymbolAddress(&wqhi, g_wqhi); cudaGetSymbolAddress(&wqlo, g_wqlo);
    cudaGetSymbolAddress(&wohi, g_wohi); cudaGetSymbolAddress(&wolo, g_wolo);
    cudaGetSymbolAddress(&qhi, g_qhi);   cudaGetSymbolAddress(&qlo, g_qlo);
    cudaGetSymbolAddress(&ahi, g_ahi);   cudaGetSymbolAddress(&alo, g_alo);
    cudaGetSymbolAddress(&khi, g_khi);   cudaGetSymbolAddress(&klo, g_klo);
    cudaGetSymbolAddress(&vhi, g_vhi);   cudaGetSymbolAddress(&vlo, g_vlo);
    cudaGetSymbolAddress(&p0, g_p0);     cudaGetSymbolAddress(&p1, g_p1);

    cudaFuncSetAttribute(gemm_bf16_sk, cudaFuncAttributeMaxDynamicSharedMemorySize, GEMM_SMEM);
    cudaFuncSetAttribute(attn_tc, cudaFuncAttributeMaxDynamicSharedMemorySize, ATT_SMEM);

    dim3 blk(256);
    conv3<<<dim3(2048, 3), blk>>>(
        (const float4*)x, (const float4*)wq, (const float4*)wo,
        (uint2*)xhi, (uint2*)xlo, (uint2*)wqhi, (uint2*)wqlo,
        (uint2*)wohi, (uint2*)wolo);
    conv_kv4<<<dim3(1024, 2), blk>>>(
        (const float4*)ck, (const float4*)cv,
        (uint2*)khi, (uint2*)klo, (uint2*)vhi, (uint2*)vlo);

    // Q projection (split-K) + fused epilogue reduce
    gemm_bf16_sk<<<dim3(32, 32, 2), blk, GEMM_SMEM>>>(
        (const uint32_t*)xhi, (const uint32_t*)xlo,
        (const uint32_t*)wqhi, (const uint32_t*)wqlo,
        (float*)p0, (float*)p1);
    reduce_qproj<<<16384, 256>>>(
        (const float4*)p0, (const float4*)p1, freqs,
        (uint32_t*)qhi, (uint32_t*)qlo);

    attn_tc<<<dim3(32, 64), dim3(128), ATT_SMEM>>>(
        (const uint32_t*)qhi, (const uint32_t*)qlo,
        (const uint32_t*)khi, (const uint32_t*)klo,
        (const uint32_t*)vhi, (const uint32_t*)vlo,
        (uint32_t*)ahi, (uint32_t*)alo);

    // Output projection (split-K) + plain reduce
    gemm_bf16_sk<<<dim3(32, 32, 2), blk, GEMM_SMEM>>>(
        (const uint32_t*)ahi, (const uint32_t*)alo,
        (const uint32_t*)wohi, (const uint32_t*)wolo,
        (float*)p0, (float*)p1);
    reduce_plain<<<16384, 256>>>(
        (const float4*)p0, (const float4*)p1, (float4*)out);
}

// round 12
// speedup vs baseline: 1.0889x; 1.0889x over previous
#include <cuda_runtime.h>
#include <cuda_bf16.h>
#include <cuda_fp16.h>
#include <math.h>
#include <stdint.h>

#define BATCH 2
#define SEQ   2048
#define DMODEL 4096
#define NHEADS 32
#define NKVH  8
#define HEADD 128
#define KVLEN 2048

// QSCALE * log2(e): softmax done in base-2
#define QSC2 (0.08838834764831845f * 1.4426950408889634f)

// ---------------------------------------------------------------------------
// Global scratch: bf16 hi/lo planes stored as packed bf16x2 (uint32).
// g_vhi holds V as packed fp16x2 (single plane); g_vlo unused.
// ---------------------------------------------------------------------------
#define PLANE_U32 (8388608)
__device__ uint32_t g_xhi[PLANE_U32],  g_xlo[PLANE_U32];   // x rows (b*s, k)
__device__ uint32_t g_wqhi[PLANE_U32], g_wqlo[PLANE_U32];  // wq (n, k)
__device__ uint32_t g_wohi[PLANE_U32], g_wolo[PLANE_U32];  // wo (n, k)
__device__ uint32_t g_qhi[PLANE_U32],  g_qlo[PLANE_U32];   // q (b,h,s,d)
__device__ uint32_t g_ahi[PLANE_U32],  g_alo[PLANE_U32];   // attn out (b*s, h*d)
#define KV_U32 (2097152)
__device__ uint32_t g_khi[KV_U32], g_klo[KV_U32];          // (b,g,s,d) bf16 hi/lo
__device__ uint32_t g_vf[KV_U32];                          // (b,g,s,d) fp16x2

// ---------------------------------------------------------------------------
__device__ __forceinline__ uint32_t smem_to_u32(const void* p) {
    uint32_t a;
    asm("{ .reg .u64 t; cvta.to.shared.u64 t, %1; cvt.u32.u64 %0, t; }" : "=r"(a) : "l"(p));
    return a;
}
#define SWZ64(off)  ((uint32_t)(off) ^ ((((uint32_t)(off)) >> 3) & 0x30u))
#define SWZ256(off) ((uint32_t)(off) ^ ((((uint32_t)(off)) >> 4) & 0x70u))

__device__ __forceinline__ void cp16(uint32_t dst, const void* src) {
    asm volatile("cp.async.cg.shared.global [%0], [%1], 16;" :: "r"(dst), "l"(src));
}
#define CP_COMMIT asm volatile("cp.async.commit_group;" ::: "memory")
#define CP_WAIT(n) asm volatile("cp.async.wait_group %0;" :: "n"(n) : "memory")

__device__ __forceinline__ void ldsm_x4(uint32_t& r0, uint32_t& r1, uint32_t& r2, uint32_t& r3,
                                        uint32_t addr) {
    asm volatile("ldmatrix.sync.aligned.m8n8.x4.shared.b16 {%0,%1,%2,%3}, [%4];"
                 : "=r"(r0), "=r"(r1), "=r"(r2), "=r"(r3) : "r"(addr));
}
__device__ __forceinline__ void ldsm_x4_t(uint32_t& r0, uint32_t& r1, uint32_t& r2, uint32_t& r3,
                                          uint32_t addr) {
    asm volatile("ldmatrix.sync.aligned.m8n8.x4.trans.shared.b16 {%0,%1,%2,%3}, [%4];"
                 : "=r"(r0), "=r"(r1), "=r"(r2), "=r"(r3) : "r"(addr));
}
__device__ __forceinline__ void mma_bf16(float* d, const uint32_t* a, uint32_t b0, uint32_t b1) {
    asm volatile(
        "mma.sync.aligned.m16n8k16.row.col.f32.bf16.bf16.f32 "
        "{%0,%1,%2,%3}, {%4,%5,%6,%7}, {%8,%9}, {%0,%1,%2,%3};"
        : "+f"(d[0]), "+f"(d[1]), "+f"(d[2]), "+f"(d[3])
        : "r"(a[0]), "r"(a[1]), "r"(a[2]), "r"(a[3]), "r"(b0), "r"(b1));
}
__device__ __forceinline__ void mma_f16(float* d, const uint32_t* a, uint32_t b0, uint32_t b1) {
    asm volatile(
        "mma.sync.aligned.m16n8k16.row.col.f32.f16.f16.f32 "
        "{%0,%1,%2,%3}, {%4,%5,%6,%7}, {%8,%9}, {%0,%1,%2,%3};"
        : "+f"(d[0]), "+f"(d[1]), "+f"(d[2]), "+f"(d[3])
        : "r"(a[0]), "r"(a[1]), "r"(a[2]), "r"(a[3]), "r"(b0), "r"(b1));
}
__device__ __forceinline__ void pack_hilo(float a, float b, uint32_t& hi, uint32_t& lo) {
    uint32_t h;
    asm("cvt.rn.bf16x2.f32 %0, %1, %2;" : "=r"(h) : "f"(b), "f"(a));
    float fa = __uint_as_float(h << 16);
    float fb = __uint_as_float(h & 0xffff0000u);
    float ra = a - fa;
    float rb = b - fb;
    uint32_t l;
    asm("cvt.rn.bf16x2.f32 %0, %1, %2;" : "=r"(l) : "f"(rb), "f"(ra));
    hi = h; lo = l;
}
__device__ __forceinline__ uint32_t pack_f16(float a, float b) {
    __half2 h = __floats2half2_rn(a, b);
    return *(uint32_t*)&h;
}

// ---------------------------------------------------------------------------
// Conversion kernels
// ---------------------------------------------------------------------------
__global__ void conv3(const float4* __restrict__ s0, const float4* __restrict__ s1,
                      const float4* __restrict__ s2,
                      uint2* h0, uint2* l0, uint2* h1, uint2* l1, uint2* h2, uint2* l2)
{
    const float4* src = (blockIdx.y == 0) ? s0 : (blockIdx.y == 1) ? s1 : s2;
    uint2* hi = (blockIdx.y == 0) ? h0 : (blockIdx.y == 1) ? h1 : h2;
    uint2* lo = (blockIdx.y == 0) ? l0 : (blockIdx.y == 1) ? l1 : l2;
    const int n4 = PLANE_U32 / 2;
    for (int i = blockIdx.x * blockDim.x + threadIdx.x; i < n4;
         i += gridDim.x * blockDim.x) {
        float4 v = src[i];
        uint32_t ha, la, hb, lb;
        pack_hilo(v.x, v.y, ha, la);
        pack_hilo(v.z, v.w, hb, lb);
        hi[i] = make_uint2(ha, hb);
        lo[i] = make_uint2(la, lb);
    }
}

// K: (b,s,g,d) fp32 -> bf16 hi/lo planes (b,g,s,d).  V: -> fp16x2 plane.
__global__ void conv_kv4(const float4* __restrict__ ksrc, const float4* __restrict__ vsrc,
                         uint2* kh, uint2* kl, uint2* vf)
{
    const int isV = blockIdx.y;
    const float4* src = isV ? vsrc : ksrc;
    const int n4 = KV_U32 / 2;
    for (int p = blockIdx.x * blockDim.x + threadIdx.x; p < n4;
         p += gridDim.x * blockDim.x) {
        const int d4 = p & 31;
        const int s = (p >> 5) & 2047;
        const int g = (p >> 16) & 7;
        const int b = p >> 19;
        float4 v = src[(((size_t)b * SEQ + s) * NKVH + g) * 32 + d4];
        if (isV) {
            vf[p] = make_uint2(pack_f16(v.x, v.y), pack_f16(v.z, v.w));
        } else {
            uint32_t ha, la, hb, lb;
            pack_hilo(v.x, v.y, ha, la);
            pack_hilo(v.z, v.w, hb, lb);
            kh[p] = make_uint2(ha, hb);
            kl[p] = make_uint2(la, lb);
        }
    }
}

// ---------------------------------------------------------------------------
// Pipelined bf16-split GEMM (PROVEN R8 config): C[M,N] = A[M,K] @ B[N,K]^T
// 3 passes. CTA 128x128, 8 warps (32x64 each), K-chunk 32,
// 3-stage cp.async (32KB stages, SW64), 2 CTAs/SM.
// EPI=0: fp32 store.  EPI=1: Q-proj (freqs * QSC2 -> bf16 hi/lo Qh/Ql).
// ---------------------------------------------------------------------------
#define GEMM_SMEM (3 * 32768)

template <int EPI>
__global__ __launch_bounds__(256, 2) void gemm_bf16(
    const uint32_t* __restrict__ Ahi, const uint32_t* __restrict__ Alo,
    const uint32_t* __restrict__ Bhi, const uint32_t* __restrict__ Blo,
    float* __restrict__ C, const float* __restrict__ freqs,
    uint32_t* __restrict__ Qh, uint32_t* __restrict__ Ql)
{
    extern __shared__ char sm[];
    const uint32_t smb = smem_to_u32(sm);
    const int tid = threadIdx.x;
    const int wid = tid >> 5;
    const int lane = tid & 31;
    const int wn = wid & 1;          // n half (64)
    const int wm = wid >> 1;         // m quarter (32)
    const int m0 = blockIdx.y * 128;
    const int n0 = blockIdx.x * 128;

    float acc[2][8][4];
#pragma unroll
    for (int i = 0; i < 2; i++)
#pragma unroll
        for (int j = 0; j < 8; j++)
#pragma unroll
            for (int v = 0; v < 4; v++) acc[i][j][v] = 0.0f;

    auto load_stage = [&](int ch, int st) {
        const uint32_t sbase = smb + (uint32_t)st * 32768u;
        const int kc2 = ch * 16;
#pragma unroll
        for (int t = tid; t < 2048; t += 256) {
            const int plane = t >> 9;            // Ahi Alo Bhi Blo
            const int i = t & 511;
            const int row = i >> 2, ck = i & 3;
            const uint32_t dst = sbase + plane * 8192u + SWZ64(row * 64 + ck * 16);
            const uint32_t* bp = (plane == 0) ? Ahi : (plane == 1) ? Alo
                                : (plane == 2) ? Bhi : Blo;
            const int r0 = (plane < 2) ? m0 : n0;
            cp16(dst, bp + (size_t)(r0 + row) * 2048 + kc2 + ck * 4);
        }
    };

    const int q = lane >> 3;
    const int wi = lane & 7;
    const int arow_base = wm * 32 + wi + ((q & 1) ? 8 : 0);
    const int akb_off = (q & 2) ? 16 : 0;
    const int brow_base = wn * 64 + wi + ((q & 2) ? 8 : 0);
    const int bkb_off = (q & 1) ? 16 : 0;

    load_stage(0, 0); CP_COMMIT;
    load_stage(1, 1); CP_COMMIT;

    for (int ch = 0; ch < 128; ++ch) {
        if (ch < 127) CP_WAIT(1); else CP_WAIT(0);
        __syncthreads();
        if (ch + 2 < 128) { load_stage(ch + 2, (ch + 2) % 3); CP_COMMIT; }

        const uint32_t sbase = smb + (uint32_t)(ch % 3) * 32768u;
        const uint32_t pAhi = sbase,           pAlo = sbase + 8192u;
        const uint32_t pBhi = sbase + 16384u,  pBlo = sbase + 24576u;

#pragma unroll
        for (int ks = 0; ks < 2; ++ks) {
            const int kb0 = ks * 32;
            uint32_t ah[2][4], al[2][4];
#pragma unroll
            for (int mt = 0; mt < 2; ++mt) {
                const int r = arow_base + mt * 16;
                const uint32_t off = SWZ64(r * 64 + kb0 + akb_off);
                ldsm_x4(ah[mt][0], ah[mt][1], ah[mt][2], ah[mt][3], pAhi + off);
                ldsm_x4(al[mt][0], al[mt][1], al[mt][2], al[mt][3], pAlo + off);
            }
#pragma unroll
            for (int np = 0; np < 4; ++np) {
                const int rn = brow_base + np * 16;
                const uint32_t offb = SWZ64(rn * 64 + kb0 + bkb_off);
                uint32_t bh[4], bl[4];
                ldsm_x4(bh[0], bh[1], bh[2], bh[3], pBhi + offb);
                ldsm_x4(bl[0], bl[1], bl[2], bl[3], pBlo + offb);
#pragma unroll
                for (int mt = 0; mt < 2; ++mt) {
                    mma_bf16(acc[mt][np * 2],     ah[mt], bh[0], bh[1]);
                    mma_bf16(acc[mt][np * 2 + 1], ah[mt], bh[2], bh[3]);
                    mma_bf16(acc[mt][np * 2],     ah[mt], bl[0], bl[1]);
                    mma_bf16(acc[mt][np * 2 + 1], ah[mt], bl[2], bl[3]);
                    mma_bf16(acc[mt][np * 2],     al[mt], bh[0], bh[1]);
                    mma_bf16(acc[mt][np * 2 + 1], al[mt], bh[2], bh[3]);
                }
            }
        }
    }

    // epilogue from registers
    const int rl = lane >> 2;
    const int cl = (lane & 3) * 2;
#pragma unroll
    for (int mt = 0; mt < 2; ++mt) {
#pragma unroll
        for (int nn = 0; nn < 8; ++nn) {
            const int r = m0 + wm * 32 + mt * 16 + rl;
            const int c = n0 + wn * 64 + nn * 8 + cl;
#pragma unroll
            for (int half = 0; half < 2; ++half) {
                const int rr = r + half * 8;
                const float v0 = acc[mt][nn][half * 2];
                const float v1 = acc[mt][nn][half * 2 + 1];
                if (EPI == 0) {
                    *(float2*)&C[(size_t)rr * DMODEL + c] = make_float2(v0, v1);
                } else {
                    const int b = rr >> 11;
                    const int s = rr & (SEQ - 1);
                    const int h = c >> 7;
                    const int d = c & (HEADD - 1);
                    float2 f = *(const float2*)&freqs[(size_t)s * 64 + (d & 63)];
                    uint32_t hi, lo;
                    pack_hilo(v0 * f.x * QSC2, v1 * f.y * QSC2, hi, lo);
                    const size_t idx = (((size_t)b * NHEADS + h) * SEQ + s) * 64 + (d >> 1);
                    Qh[idx] = hi; Ql[idx] = lo;
                }
            }
        }
    }
}

// ---------------------------------------------------------------------------
// Tensor-core flash attention (causal). S = bf16 hi/lo 3-pass (base-2 softmax);
// PV = single-pass fp16 (P,V fp16). CTA: 64 q-rows, 4 warps, KV blocks of 32.
// Stages: 3 x 24KB (Khi 8K | Klo 8K | Vf16 8K); Q in dedicated 32KB area.
// 2 CTAs/SM.
// ---------------------------------------------------------------------------
#define ATT_QOFF 73728u
#define ATT_SMEM (73728 + 32768)

__global__ __launch_bounds__(128, 2) void attn_tc(
    const uint32_t* __restrict__ Qhi, const uint32_t* __restrict__ Qlo,
    const uint32_t* __restrict__ Khi, const uint32_t* __restrict__ Klo,
    const uint32_t* __restrict__ Vf,
    uint32_t* __restrict__ Ohi, uint32_t* __restrict__ Olo)
{
    extern __shared__ char sm[];
    const uint32_t smb = smem_to_u32(sm);
    const int tid = threadIdx.x;
    const int w = tid >> 5;
    const int lane = tid & 31;
    const int bx = gridDim.x - 1 - blockIdx.x;   // big tiles first
    const int by = blockIdx.y;
    const int b = by >> 5, h = by & 31, g = h >> 2;
    const int q0 = bx * 64;
    const int nb = 2 * bx + 2;                   // KV blocks of 32 rows

    // --- Q load (64 rows x 2 planes = 32KB) into dedicated area ---
    const size_t qbase = (((size_t)b * NHEADS + h) * SEQ + q0) * 64;
#pragma unroll
    for (int t = tid; t < 2048; t += 128) {
        const int plane = t >> 10;
        const int i = t & 1023;
        const int row = i >> 4, ck = i & 15;
        const uint32_t dst = smb + ATT_QOFF + plane * 16384u + SWZ256(row * 256 + ck * 16);
        cp16(dst, (plane ? Qlo : Qhi) + qbase + (size_t)row * 64 + ck * 4);
    }
    CP_COMMIT;

    const size_t kvbase = ((size_t)b * NKVH + g) * KVLEN * 64;
    auto load_kv = [&](int jb, int region) {
        const uint32_t sb = smb + (uint32_t)region * 24576u;
        const int kv0 = jb * 32;
#pragma unroll
        for (int t = tid; t < 1536; t += 128) {
            const int plane = t >> 9;                 // Khi Klo Vf
            const int i = t & 511;
            const int row = i >> 4, ck = i & 15;
            const uint32_t dst = sb + plane * 8192u + SWZ256(row * 256 + ck * 16);
            const uint32_t* base = (plane == 0) ? Khi : (plane == 1) ? Klo : Vf;
            cp16(dst, base + kvbase + (size_t)(kv0 + row) * 64 + ck * 4);
        }
    };

    load_kv(0, 0); CP_COMMIT;
    load_kv(1, 1); CP_COMMIT;
    CP_WAIT(2);                 // Q done
    __syncthreads();

    // --- preload Q fragments (Q area is persistent; no recycle sync needed) ---
    const int wi = lane & 7, qq = lane >> 3;
    const int arow = w * 16 + wi + ((qq & 1) ? 8 : 0);
    const int akoff = (qq & 2) ? 16 : 0;
    uint32_t qh[8][4], ql[8][4];
#pragma unroll
    for (int ks = 0; ks < 8; ks++) {
        const uint32_t off = SWZ256(arow * 256 + ks * 32 + akoff);
        ldsm_x4(qh[ks][0], qh[ks][1], qh[ks][2], qh[ks][3], smb + ATT_QOFF + off);
        ldsm_x4(ql[ks][0], ql[ks][1], ql[ks][2], ql[ks][3], smb + ATT_QOFF + 16384u + off);
    }

    float oacc[16][4];
#pragma unroll
    for (int i = 0; i < 16; i++)
#pragma unroll
        for (int v = 0; v < 4; v++) oacc[i][v] = 0.0f;
    float mprev0 = -INFINITY, mprev1 = -INFINITY;
    float lsum0 = 0.0f, lsum1 = 0.0f;

    const int rl = lane >> 2, cl2 = (lane & 3) * 2;
    const int row0g = q0 + w * 16 + rl;
    const int row1g = row0g + 8;
    const int brow = wi + ((qq & 2) ? 8 : 0);
    const int bkoff = (qq & 1) ? 16 : 0;
    const int vkr = (lane & 7) + ((lane & 8) ? 8 : 0);
    const int vnoff = (lane & 16) ? 16 : 0;

    for (int jb = 0; jb < nb; ++jb) {
        if (jb < nb - 1) CP_WAIT(1); else CP_WAIT(0);
        __syncthreads();
        if (jb + 2 < nb) { load_kv(jb + 2, (jb + 2) % 3); CP_COMMIT; }
        const uint32_t sb = smb + (uint32_t)(jb % 3) * 24576u;

        // --- S = Q @ K^T (3-pass), scores in log2 domain ---
        float sacc[4][4];
#pragma unroll
        for (int i = 0; i < 4; i++)
#pragma unroll
            for (int v = 0; v < 4; v++) sacc[i][v] = 0.0f;
#pragma unroll
        for (int ks = 0; ks < 8; ks++) {
#pragma unroll
            for (int nt2 = 0; nt2 < 2; nt2++) {
                const uint32_t off = SWZ256((nt2 * 16 + brow) * 256 + ks * 32 + bkoff);
                uint32_t bh[4], bl[4];
                ldsm_x4(bh[0], bh[1], bh[2], bh[3], sb + off);
                ldsm_x4(bl[0], bl[1], bl[2], bl[3], sb + 8192u + off);
                mma_bf16(sacc[nt2 * 2],     qh[ks], bh[0], bh[1]);
                mma_bf16(sacc[nt2 * 2 + 1], qh[ks], bh[2], bh[3]);
                mma_bf16(sacc[nt2 * 2],     qh[ks], bl[0], bl[1]);
                mma_bf16(sacc[nt2 * 2 + 1], qh[ks], bl[2], bl[3]);
                mma_bf16(sacc[nt2 * 2],     ql[ks], bh[0], bh[1]);
                mma_bf16(sacc[nt2 * 2 + 1], ql[ks], bh[2], bh[3]);
            }
        }

        // --- causal mask ---
        if (jb >= 2 * bx) {
            const int kv0 = jb * 32;
#pragma unroll
            for (int nt = 0; nt < 4; nt++) {
                const int c0 = kv0 + nt * 8 + cl2;
                const int c1 = c0 + 1;
                if (c0 > row0g) sacc[nt][0] = -1e30f;
                if (c1 > row0g) sacc[nt][1] = -1e30f;
                if (c0 > row1g) sacc[nt][2] = -1e30f;
                if (c1 > row1g) sacc[nt][3] = -1e30f;
            }
        }

        // --- online softmax (base 2) ---
        float mx0 = -1e30f, mx1 = -1e30f;
#pragma unroll
        for (int nt = 0; nt < 4; nt++) {
            mx0 = fmaxf(mx0, fmaxf(sacc[nt][0], sacc[nt][1]));
            mx1 = fmaxf(mx1, fmaxf(sacc[nt][2], sacc[nt][3]));
        }
        mx0 = fmaxf(mx0, __shfl_xor_sync(0xffffffffu, mx0, 1));
        mx0 = fmaxf(mx0, __shfl_xor_sync(0xffffffffu, mx0, 2));
        mx1 = fmaxf(mx1, __shfl_xor_sync(0xffffffffu, mx1, 1));
        mx1 = fmaxf(mx1, __shfl_xor_sync(0xffffffffu, mx1, 2));
        const float mnew0 = fmaxf(mprev0, mx0);
        const float mnew1 = fmaxf(mprev1, mx1);
        const float alpha0 = exp2f(mprev0 - mnew0);
        const float alpha1 = exp2f(mprev1 - mnew1);
        float rs0 = 0.0f, rs1 = 0.0f;
#pragma unroll
        for (int nt = 0; nt < 4; nt++) {
            sacc[nt][0] = exp2f(sacc[nt][0] - mnew0);
            sacc[nt][1] = exp2f(sacc[nt][1] - mnew0);
            sacc[nt][2] = exp2f(sacc[nt][2] - mnew1);
            sacc[nt][3] = exp2f(sacc[nt][3] - mnew1);
            rs0 += sacc[nt][0] + sacc[nt][1];
            rs1 += sacc[nt][2] + sacc[nt][3];
        }
        rs0 += __shfl_xor_sync(0xffffffffu, rs0, 1);
        rs0 += __shfl_xor_sync(0xffffffffu, rs0, 2);
        rs1 += __shfl_xor_sync(0xffffffffu, rs1, 1);
        rs1 += __shfl_xor_sync(0xffffffffu, rs1, 2);
        lsum0 = lsum0 * alpha0 + rs0;
        lsum1 = lsum1 * alpha1 + rs1;
#pragma unroll
        for (int nt = 0; nt < 16; nt++) {
            oacc[nt][0] *= alpha0; oacc[nt][1] *= alpha0;
            oacc[nt][2] *= alpha1; oacc[nt][3] *= alpha1;
        }
        mprev0 = mnew0; mprev1 = mnew1;

        // --- O += P @ V (single-pass fp16) ---
#pragma unroll
        for (int jp = 0; jp < 2; jp++) {
            uint32_t pf[4];
            pf[0] = pack_f16(sacc[2 * jp][0],     sacc[2 * jp][1]);
            pf[1] = pack_f16(sacc[2 * jp][2],     sacc[2 * jp][3]);
            pf[2] = pack_f16(sacc[2 * jp + 1][0], sacc[2 * jp + 1][1]);
            pf[3] = pack_f16(sacc[2 * jp + 1][2], sacc[2 * jp + 1][3]);
#pragma unroll
            for (int nt2 = 0; nt2 < 8; nt2++) {
                const uint32_t off = SWZ256((jp * 16 + vkr) * 256 + nt2 * 32 + vnoff);
                uint32_t vh[4];
                ldsm_x4_t(vh[0], vh[1], vh[2], vh[3], sb + 16384u + off);
                mma_f16(oacc[nt2 * 2],     pf, vh[0], vh[1]);
                mma_f16(oacc[nt2 * 2 + 1], pf, vh[2], vh[3]);
            }
        }
    }

    // --- epilogue ---
    const float inv0 = 1.0f / lsum0;
    const float inv1 = 1.0f / lsum1;
    const size_t r0 = ((size_t)b * SEQ + row0g) * 2048 + h * 64;
    const size_t r1 = ((size_t)b * SEQ + row1g) * 2048 + h * 64;
#pragma unroll
    for (int nt = 0; nt < 16; nt++) {
        const int d2 = (nt * 8 + cl2) >> 1;
        uint32_t hi0, lo0, hi1, lo1;
        pack_hilo(oacc[nt][0] * inv0, oacc[nt][1] * inv0, hi0, lo0);
        pack_hilo(oacc[nt][2] * inv1, oacc[nt][3] * inv1, hi1, lo1);
        Ohi[r0 + d2] = hi0; Olo[r0 + d2] = lo0;
        Ohi[r1 + d2] = hi1; Olo[r1 + d2] = lo1;
    }
}

// ---------------------------------------------------------------------------
extern "C" void kernel_launch(void* const* d_in, const int* in_sizes, int n_in,
                              void* d_out, int out_size)
{
    (void)in_sizes; (void)n_in; (void)out_size;
    const float* x     = (const float*)d_in[0];
    const float* freqs = (const float*)d_in[1];
    const float* wq    = (const float*)d_in[3];
    const float* wo    = (const float*)d_in[6];
    const float* ck    = (const float*)d_in[7];
    const float* cv    = (const float*)d_in[8];
    float* out = (float*)d_out;

    void *xhi, *xlo, *wqhi, *wqlo, *wohi, *wolo, *qhi, *qlo, *ahi, *alo;
    void *khi, *klo, *vf;
    cudaGetSymbolAddress(&xhi, g_xhi);   cudaGetSymbolAddress(&xlo, g_xlo);
    cudaGetSymbolAddress(&wqhi, g_wqhi); cudaGetSymbolAddress(&wqlo, g_wqlo);
    cudaGetSymbolAddress(&wohi, g_wohi); cudaGetSymbolAddress(&wolo, g_wolo);
    cudaGetSymbolAddress(&qhi, g_qhi);   cudaGetSymbolAddress(&qlo, g_qlo);
    cudaGetSymbolAddress(&ahi, g_ahi);   cudaGetSymbolAddress(&alo, g_alo);
    cudaGetSymbolAddress(&khi, g_khi);   cudaGetSymbolAddress(&klo, g_klo);
    cudaGetSymbolAddress(&vf, g_vf);

    cudaFuncSetAttribute(gemm_bf16<0>, cudaFuncAttributeMaxDynamicSharedMemorySize, GEMM_SMEM);
    cudaFuncSetAttribute(gemm_bf16<1>, cudaFuncAttributeMaxDynamicSharedMemorySize, GEMM_SMEM);
    cudaFuncSetAttribute(attn_tc, cudaFuncAttributeMaxDynamicSharedMemorySize, ATT_SMEM);

    dim3 blk(256);
    conv3<<<dim3(2048, 3), blk>>>(
        (const float4*)x, (const float4*)wq, (const float4*)wo,
        (uint2*)xhi, (uint2*)xlo, (uint2*)wqhi, (uint2*)wqlo,
        (uint2*)wohi, (uint2*)wolo);
    conv_kv4<<<dim3(1024, 2), blk>>>(
        (const float4*)ck, (const float4*)cv,
        (uint2*)khi, (uint2*)klo, (uint2*)vf);

    gemm_bf16<1><<<dim3(32, 32), blk, GEMM_SMEM>>>(
        (const uint32_t*)xhi, (const uint32_t*)xlo,
        (const uint32_t*)wqhi, (const uint32_t*)wqlo,
        nullptr, freqs, (uint32_t*)qhi, (uint32_t*)qlo);

    attn_tc<<<dim3(32, 64), dim3(128), ATT_SMEM>>>(
        (const uint32_t*)qhi, (const uint32_t*)qlo,
        (const uint32_t*)khi, (const uint32_t*)klo,
        (const uint32_t*)vf,
        (uint32_t*)ahi, (uint32_t*)alo);

    gemm_bf16<0><<<dim3(32, 32), blk, GEMM_SMEM>>>(
        (const uint32_t*)ahi, (const uint32_t*)alo,
        (const uint32_t*)wohi, (const uint32_t*)wolo,
        out, nullptr, nullptr, nullptr);
}

// round 13
// speedup vs baseline: 1.2477x; 1.1458x over previous
#include <cuda_runtime.h>
#include <cuda_bf16.h>
#include <cuda_fp16.h>
#include <math.h>
#include <stdint.h>

#define BATCH 2
#define SEQ   2048
#define DMODEL 4096
#define NHEADS 32
#define NKVH  8
#define HEADD 128
#define KVLEN 2048

// QSCALE * log2(e): softmax done in base-2
#define QSC2 (0.08838834764831845f * 1.4426950408889634f)

// ---------------------------------------------------------------------------
// Global scratch.
// x/wq: bf16 hi/lo planes. wo: fp16 hi/lo planes. K: bf16 hi/lo. V: fp16.
// attn out: single fp16 plane (g_af).
// ---------------------------------------------------------------------------
#define PLANE_U32 (8388608)
__device__ uint32_t g_xhi[PLANE_U32],  g_xlo[PLANE_U32];   // x (b*s, k) bf16
__device__ uint32_t g_wqhi[PLANE_U32], g_wqlo[PLANE_U32];  // wq (n, k) bf16
__device__ uint32_t g_wohi[PLANE_U32], g_wolo[PLANE_U32];  // wo (n, k) fp16 hi/lo
__device__ uint32_t g_qhi[PLANE_U32],  g_qlo[PLANE_U32];   // q (b,h,s,d) bf16
__device__ uint32_t g_af[PLANE_U32];                       // attn out (b*s, h*d) fp16
#define KV_U32 (2097152)
__device__ uint32_t g_khi[KV_U32], g_klo[KV_U32];          // (b,g,s,d) bf16 hi/lo
__device__ uint32_t g_vf[KV_U32];                          // (b,g,s,d) fp16x2

// ---------------------------------------------------------------------------
__device__ __forceinline__ uint32_t smem_to_u32(const void* p) {
    uint32_t a;
    asm("{ .reg .u64 t; cvta.to.shared.u64 t, %1; cvt.u32.u64 %0, t; }" : "=r"(a) : "l"(p));
    return a;
}
#define SWZ64(off)  ((uint32_t)(off) ^ ((((uint32_t)(off)) >> 3) & 0x30u))
#define SWZ256(off) ((uint32_t)(off) ^ ((((uint32_t)(off)) >> 4) & 0x70u))

__device__ __forceinline__ void cp16(uint32_t dst, const void* src) {
    asm volatile("cp.async.cg.shared.global [%0], [%1], 16;" :: "r"(dst), "l"(src));
}
#define CP_COMMIT asm volatile("cp.async.commit_group;" ::: "memory")
#define CP_WAIT(n) asm volatile("cp.async.wait_group %0;" :: "n"(n) : "memory")

__device__ __forceinline__ void ldsm_x4(uint32_t& r0, uint32_t& r1, uint32_t& r2, uint32_t& r3,
                                        uint32_t addr) {
    asm volatile("ldmatrix.sync.aligned.m8n8.x4.shared.b16 {%0,%1,%2,%3}, [%4];"
                 : "=r"(r0), "=r"(r1), "=r"(r2), "=r"(r3) : "r"(addr));
}
__device__ __forceinline__ void ldsm_x4_t(uint32_t& r0, uint32_t& r1, uint32_t& r2, uint32_t& r3,
                                          uint32_t addr) {
    asm volatile("ldmatrix.sync.aligned.m8n8.x4.trans.shared.b16 {%0,%1,%2,%3}, [%4];"
                 : "=r"(r0), "=r"(r1), "=r"(r2), "=r"(r3) : "r"(addr));
}
__device__ __forceinline__ void mma_bf16(float* d, const uint32_t* a, uint32_t b0, uint32_t b1) {
    asm volatile(
        "mma.sync.aligned.m16n8k16.row.col.f32.bf16.bf16.f32 "
        "{%0,%1,%2,%3}, {%4,%5,%6,%7}, {%8,%9}, {%0,%1,%2,%3};"
        : "+f"(d[0]), "+f"(d[1]), "+f"(d[2]), "+f"(d[3])
        : "r"(a[0]), "r"(a[1]), "r"(a[2]), "r"(a[3]), "r"(b0), "r"(b1));
}
__device__ __forceinline__ void mma_f16(float* d, const uint32_t* a, uint32_t b0, uint32_t b1) {
    asm volatile(
        "mma.sync.aligned.m16n8k16.row.col.f32.f16.f16.f32 "
        "{%0,%1,%2,%3}, {%4,%5,%6,%7}, {%8,%9}, {%0,%1,%2,%3};"
        : "+f"(d[0]), "+f"(d[1]), "+f"(d[2]), "+f"(d[3])
        : "r"(a[0]), "r"(a[1]), "r"(a[2]), "r"(a[3]), "r"(b0), "r"(b1));
}
__device__ __forceinline__ void pack_hilo(float a, float b, uint32_t& hi, uint32_t& lo) {
    uint32_t h;
    asm("cvt.rn.bf16x2.f32 %0, %1, %2;" : "=r"(h) : "f"(b), "f"(a));
    float fa = __uint_as_float(h << 16);
    float fb = __uint_as_float(h & 0xffff0000u);
    float ra = a - fa;
    float rb = b - fb;
    uint32_t l;
    asm("cvt.rn.bf16x2.f32 %0, %1, %2;" : "=r"(l) : "f"(rb), "f"(ra));
    hi = h; lo = l;
}
__device__ __forceinline__ uint32_t pack_f16(float a, float b) {
    __half2 h = __floats2half2_rn(a, b);
    return *(uint32_t*)&h;
}
__device__ __forceinline__ void pack_f16_hilo(float a, float b, uint32_t& hi, uint32_t& lo) {
    __half2 h = __floats2half2_rn(a, b);
    float2 hf = __half22float2(h);
    __half2 l = __floats2half2_rn(a - hf.x, b - hf.y);
    hi = *(uint32_t*)&h;
    lo = *(uint32_t*)&l;
}

// ---------------------------------------------------------------------------
// Conversion kernels
// ---------------------------------------------------------------------------
// y=0: x (bf16 hi/lo), y=1: wq (bf16 hi/lo), y=2: wo (fp16 hi/lo)
__global__ void conv3(const float4* __restrict__ s0, const float4* __restrict__ s1,
                      const float4* __restrict__ s2,
                      uint2* h0, uint2* l0, uint2* h1, uint2* l1, uint2* h2, uint2* l2)
{
    const int mode = blockIdx.y;
    const float4* src = (mode == 0) ? s0 : (mode == 1) ? s1 : s2;
    uint2* hi = (mode == 0) ? h0 : (mode == 1) ? h1 : h2;
    uint2* lo = (mode == 0) ? l0 : (mode == 1) ? l1 : l2;
    const int n4 = PLANE_U32 / 2;
    for (int i = blockIdx.x * blockDim.x + threadIdx.x; i < n4;
         i += gridDim.x * blockDim.x) {
        float4 v = src[i];
        uint32_t ha, la, hb, lb;
        if (mode == 2) {
            pack_f16_hilo(v.x, v.y, ha, la);
            pack_f16_hilo(v.z, v.w, hb, lb);
        } else {
            pack_hilo(v.x, v.y, ha, la);
            pack_hilo(v.z, v.w, hb, lb);
        }
        hi[i] = make_uint2(ha, hb);
        lo[i] = make_uint2(la, lb);
    }
}

// K: (b,s,g,d) fp32 -> bf16 hi/lo planes (b,g,s,d).  V: -> fp16x2 plane.
__global__ void conv_kv4(const float4* __restrict__ ksrc, const float4* __restrict__ vsrc,
                         uint2* kh, uint2* kl, uint2* vf)
{
    const int isV = blockIdx.y;
    const float4* src = isV ? vsrc : ksrc;
    const int n4 = KV_U32 / 2;
    for (int p = blockIdx.x * blockDim.x + threadIdx.x; p < n4;
         p += gridDim.x * blockDim.x) {
        const int d4 = p & 31;
        const int s = (p >> 5) & 2047;
        const int g = (p >> 16) & 7;
        const int b = p >> 19;
        float4 v = src[(((size_t)b * SEQ + s) * NKVH + g) * 32 + d4];
        if (isV) {
            vf[p] = make_uint2(pack_f16(v.x, v.y), pack_f16(v.z, v.w));
        } else {
            uint32_t ha, la, hb, lb;
            pack_hilo(v.x, v.y, ha, la);
            pack_hilo(v.z, v.w, hb, lb);
            kh[p] = make_uint2(ha, hb);
            kl[p] = make_uint2(la, lb);
        }
    }
}

// ---------------------------------------------------------------------------
// 3-pass bf16-split GEMM (Q projection, proven R8 config).
// CTA 128x128, 8 warps (32x64), K-chunk 32, 3x32KB stages SW64, 2 CTAs/SM.
// Epilogue: Q-proj (freqs * QSC2 -> bf16 hi/lo Qh/Ql).
// ---------------------------------------------------------------------------
#define GEMM_SMEM (3 * 32768)

__global__ __launch_bounds__(256, 2) void gemm_qproj(
    const uint32_t* __restrict__ Ahi, const uint32_t* __restrict__ Alo,
    const uint32_t* __restrict__ Bhi, const uint32_t* __restrict__ Blo,
    const float* __restrict__ freqs,
    uint32_t* __restrict__ Qh, uint32_t* __restrict__ Ql)
{
    extern __shared__ char sm[];
    const uint32_t smb = smem_to_u32(sm);
    const int tid = threadIdx.x;
    const int wid = tid >> 5;
    const int lane = tid & 31;
    const int wn = wid & 1;
    const int wm = wid >> 1;
    const int m0 = blockIdx.y * 128;
    const int n0 = blockIdx.x * 128;

    float acc[2][8][4];
#pragma unroll
    for (int i = 0; i < 2; i++)
#pragma unroll
        for (int j = 0; j < 8; j++)
#pragma unroll
            for (int v = 0; v < 4; v++) acc[i][j][v] = 0.0f;

    auto load_stage = [&](int ch, int st) {
        const uint32_t sbase = smb + (uint32_t)st * 32768u;
        const int kc2 = ch * 16;
#pragma unroll
        for (int t = tid; t < 2048; t += 256) {
            const int plane = t >> 9;            // Ahi Alo Bhi Blo
            const int i = t & 511;
            const int row = i >> 2, ck = i & 3;
            const uint32_t dst = sbase + plane * 8192u + SWZ64(row * 64 + ck * 16);
            const uint32_t* bp = (plane == 0) ? Ahi : (plane == 1) ? Alo
                                : (plane == 2) ? Bhi : Blo;
            const int r0 = (plane < 2) ? m0 : n0;
            cp16(dst, bp + (size_t)(r0 + row) * 2048 + kc2 + ck * 4);
        }
    };

    const int q = lane >> 3;
    const int wi = lane & 7;
    const int arow_base = wm * 32 + wi + ((q & 1) ? 8 : 0);
    const int akb_off = (q & 2) ? 16 : 0;
    const int brow_base = wn * 64 + wi + ((q & 2) ? 8 : 0);
    const int bkb_off = (q & 1) ? 16 : 0;

    load_stage(0, 0); CP_COMMIT;
    load_stage(1, 1); CP_COMMIT;

    for (int ch = 0; ch < 128; ++ch) {
        if (ch < 127) CP_WAIT(1); else CP_WAIT(0);
        __syncthreads();
        if (ch + 2 < 128) { load_stage(ch + 2, (ch + 2) % 3); CP_COMMIT; }

        const uint32_t sbase = smb + (uint32_t)(ch % 3) * 32768u;
        const uint32_t pAhi = sbase,           pAlo = sbase + 8192u;
        const uint32_t pBhi = sbase + 16384u,  pBlo = sbase + 24576u;

#pragma unroll
        for (int ks = 0; ks < 2; ++ks) {
            const int kb0 = ks * 32;
            uint32_t ah[2][4], al[2][4];
#pragma unroll
            for (int mt = 0; mt < 2; ++mt) {
                const int r = arow_base + mt * 16;
                const uint32_t off = SWZ64(r * 64 + kb0 + akb_off);
                ldsm_x4(ah[mt][0], ah[mt][1], ah[mt][2], ah[mt][3], pAhi + off);
                ldsm_x4(al[mt][0], al[mt][1], al[mt][2], al[mt][3], pAlo + off);
            }
#pragma unroll
            for (int np = 0; np < 4; ++np) {
                const int rn = brow_base + np * 16;
                const uint32_t offb = SWZ64(rn * 64 + kb0 + bkb_off);
                uint32_t bh[4], bl[4];
                ldsm_x4(bh[0], bh[1], bh[2], bh[3], pBhi + offb);
                ldsm_x4(bl[0], bl[1], bl[2], bl[3], pBlo + offb);
#pragma unroll
                for (int mt = 0; mt < 2; ++mt) {
                    mma_bf16(acc[mt][np * 2],     ah[mt], bh[0], bh[1]);
                    mma_bf16(acc[mt][np * 2 + 1], ah[mt], bh[2], bh[3]);
                    mma_bf16(acc[mt][np * 2],     ah[mt], bl[0], bl[1]);
                    mma_bf16(acc[mt][np * 2 + 1], ah[mt], bl[2], bl[3]);
                    mma_bf16(acc[mt][np * 2],     al[mt], bh[0], bh[1]);
                    mma_bf16(acc[mt][np * 2 + 1], al[mt], bh[2], bh[3]);
                }
            }
        }
    }

    const int rl = lane >> 2;
    const int cl = (lane & 3) * 2;
#pragma unroll
    for (int mt = 0; mt < 2; ++mt) {
#pragma unroll
        for (int nn = 0; nn < 8; ++nn) {
            const int r = m0 + wm * 32 + mt * 16 + rl;
            const int c = n0 + wn * 64 + nn * 8 + cl;
#pragma unroll
            for (int half = 0; half < 2; ++half) {
                const int rr = r + half * 8;
                const float v0 = acc[mt][nn][half * 2];
                const float v1 = acc[mt][nn][half * 2 + 1];
                const int b = rr >> 11;
                const int s = rr & (SEQ - 1);
                const int h = c >> 7;
                const int d = c & (HEADD - 1);
                float2 f = *(const float2*)&freqs[(size_t)s * 64 + (d & 63)];
                uint32_t hi, lo;
                pack_hilo(v0 * f.x * QSC2, v1 * f.y * QSC2, hi, lo);
                const size_t idx = (((size_t)b * NHEADS + h) * SEQ + s) * 64 + (d >> 1);
                Qh[idx] = hi; Ql[idx] = lo;
            }
        }
    }
}

// ---------------------------------------------------------------------------
// 2-pass fp16 GEMM (O projection): C = Af @ (Wh + Wl)^T.
// A single fp16 plane; B fp16 hi/lo. Same tile shape as above.
// Stages: 3 x 24KB (Af 8K | Bhi 8K | Blo 8K).
// ---------------------------------------------------------------------------
#define GEMM2_SMEM (3 * 24576)

__global__ __launch_bounds__(256, 2) void gemm_oproj(
    const uint32_t* __restrict__ Af,
    const uint32_t* __restrict__ Bhi, const uint32_t* __restrict__ Blo,
    float* __restrict__ C)
{
    extern __shared__ char sm[];
    const uint32_t smb = smem_to_u32(sm);
    const int tid = threadIdx.x;
    const int wid = tid >> 5;
    const int lane = tid & 31;
    const int wn = wid & 1;
    const int wm = wid >> 1;
    const int m0 = blockIdx.y * 128;
    const int n0 = blockIdx.x * 128;

    float acc[2][8][4];
#pragma unroll
    for (int i = 0; i < 2; i++)
#pragma unroll
        for (int j = 0; j < 8; j++)
#pragma unroll
            for (int v = 0; v < 4; v++) acc[i][j][v] = 0.0f;

    auto load_stage = [&](int ch, int st) {
        const uint32_t sbase = smb + (uint32_t)st * 24576u;
        const int kc2 = ch * 16;
#pragma unroll
        for (int t = tid; t < 1536; t += 256) {
            const int plane = t >> 9;            // Af Bhi Blo
            const int i = t & 511;
            const int row = i >> 2, ck = i & 3;
            const uint32_t dst = sbase + plane * 8192u + SWZ64(row * 64 + ck * 16);
            const uint32_t* bp = (plane == 0) ? Af : (plane == 1) ? Bhi : Blo;
            const int r0 = (plane == 0) ? m0 : n0;
            cp16(dst, bp + (size_t)(r0 + row) * 2048 + kc2 + ck * 4);
        }
    };

    const int q = lane >> 3;
    const int wi = lane & 7;
    const int arow_base = wm * 32 + wi + ((q & 1) ? 8 : 0);
    const int akb_off = (q & 2) ? 16 : 0;
    const int brow_base = wn * 64 + wi + ((q & 2) ? 8 : 0);
    const int bkb_off = (q & 1) ? 16 : 0;

    load_stage(0, 0); CP_COMMIT;
    load_stage(1, 1); CP_COMMIT;

    for (int ch = 0; ch < 128; ++ch) {
        if (ch < 127) CP_WAIT(1); else CP_WAIT(0);
        __syncthreads();
        if (ch + 2 < 128) { load_stage(ch + 2, (ch + 2) % 3); CP_COMMIT; }

        const uint32_t sbase = smb + (uint32_t)(ch % 3) * 24576u;
        const uint32_t pAf = sbase;
        const uint32_t pBhi = sbase + 8192u, pBlo = sbase + 16384u;

#pragma unroll
        for (int ks = 0; ks < 2; ++ks) {
            const int kb0 = ks * 32;
            uint32_t af[2][4];
#pragma unroll
            for (int mt = 0; mt < 2; ++mt) {
                const int r = arow_base + mt * 16;
                const uint32_t off = SWZ64(r * 64 + kb0 + akb_off);
                ldsm_x4(af[mt][0], af[mt][1], af[mt][2], af[mt][3], pAf + off);
            }
#pragma unroll
            for (int np = 0; np < 4; ++np) {
                const int rn = brow_base + np * 16;
                const uint32_t offb = SWZ64(rn * 64 + kb0 + bkb_off);
                uint32_t bh[4], bl[4];
                ldsm_x4(bh[0], bh[1], bh[2], bh[3], pBhi + offb);
                ldsm_x4(bl[0], bl[1], bl[2], bl[3], pBlo + offb);
#pragma unroll
                for (int mt = 0; mt < 2; ++mt) {
                    mma_f16(acc[mt][np * 2],     af[mt], bh[0], bh[1]);
                    mma_f16(acc[mt][np * 2 + 1], af[mt], bh[2], bh[3]);
                    mma_f16(acc[mt][np * 2],     af[mt], bl[0], bl[1]);
                    mma_f16(acc[mt][np * 2 + 1], af[mt], bl[2], bl[3]);
                }
            }
        }
    }

    const int rl = lane >> 2;
    const int cl = (lane & 3) * 2;
#pragma unroll
    for (int mt = 0; mt < 2; ++mt) {
#pragma unroll
        for (int nn = 0; nn < 8; ++nn) {
            const int r = m0 + wm * 32 + mt * 16 + rl;
            const int c = n0 + wn * 64 + nn * 8 + cl;
#pragma unroll
            for (int half = 0; half < 2; ++half) {
                const int rr = r + half * 8;
                *(float2*)&C[(size_t)rr * DMODEL + c] =
                    make_float2(acc[mt][nn][half * 2], acc[mt][nn][half * 2 + 1]);
            }
        }
    }
}

// ---------------------------------------------------------------------------
// Tensor-core flash attention (causal). S = bf16 hi/lo 3-pass (base-2 softmax);
// PV = single-pass fp16. Output -> single fp16 plane.
// CTA: 64 q-rows, 4 warps, KV blocks of 32. Stages 3x24KB + Q 32KB. 2 CTAs/SM.
// ---------------------------------------------------------------------------
#define ATT_QOFF 73728u
#define ATT_SMEM (73728 + 32768)

__global__ __launch_bounds__(128, 2) void attn_tc(
    const uint32_t* __restrict__ Qhi, const uint32_t* __restrict__ Qlo,
    const uint32_t* __restrict__ Khi, const uint32_t* __restrict__ Klo,
    const uint32_t* __restrict__ Vf,
    uint32_t* __restrict__ Of)
{
    extern __shared__ char sm[];
    const uint32_t smb = smem_to_u32(sm);
    const int tid = threadIdx.x;
    const int w = tid >> 5;
    const int lane = tid & 31;
    const int bx = gridDim.x - 1 - blockIdx.x;   // big tiles first
    const int by = blockIdx.y;
    const int b = by >> 5, h = by & 31, g = h >> 2;
    const int q0 = bx * 64;
    const int nb = 2 * bx + 2;                   // KV blocks of 32 rows

    // --- Q load (64 rows x 2 planes = 32KB) into dedicated area ---
    const size_t qbase = (((size_t)b * NHEADS + h) * SEQ + q0) * 64;
#pragma unroll
    for (int t = tid; t < 2048; t += 128) {
        const int plane = t >> 10;
        const int i = t & 1023;
        const int row = i >> 4, ck = i & 15;
        const uint32_t dst = smb + ATT_QOFF + plane * 16384u + SWZ256(row * 256 + ck * 16);
        cp16(dst, (plane ? Qlo : Qhi) + qbase + (size_t)row * 64 + ck * 4);
    }
    CP_COMMIT;

    const size_t kvbase = ((size_t)b * NKVH + g) * KVLEN * 64;
    auto load_kv = [&](int jb, int region) {
        const uint32_t sb = smb + (uint32_t)region * 24576u;
        const int kv0 = jb * 32;
#pragma unroll
        for (int t = tid; t < 1536; t += 128) {
            const int plane = t >> 9;                 // Khi Klo Vf
            const int i = t & 511;
            const int row = i >> 4, ck = i & 15;
            const uint32_t dst = sb + plane * 8192u + SWZ256(row * 256 + ck * 16);
            const uint32_t* base = (plane == 0) ? Khi : (plane == 1) ? Klo : Vf;
            cp16(dst, base + kvbase + (size_t)(kv0 + row) * 64 + ck * 4);
        }
    };

    load_kv(0, 0); CP_COMMIT;
    load_kv(1, 1); CP_COMMIT;
    CP_WAIT(2);                 // Q done
    __syncthreads();

    // --- preload Q fragments (Q area persistent) ---
    const int wi = lane & 7, qq = lane >> 3;
    const int arow = w * 16 + wi + ((qq & 1) ? 8 : 0);
    const int akoff = (qq & 2) ? 16 : 0;
    uint32_t qh[8][4], ql[8][4];
#pragma unroll
    for (int ks = 0; ks < 8; ks++) {
        const uint32_t off = SWZ256(arow * 256 + ks * 32 + akoff);
        ldsm_x4(qh[ks][0], qh[ks][1], qh[ks][2], qh[ks][3], smb + ATT_QOFF + off);
        ldsm_x4(ql[ks][0], ql[ks][1], ql[ks][2], ql[ks][3], smb + ATT_QOFF + 16384u + off);
    }

    float oacc[16][4];
#pragma unroll
    for (int i = 0; i < 16; i++)
#pragma unroll
        for (int v = 0; v < 4; v++) oacc[i][v] = 0.0f;
    float mprev0 = -INFINITY, mprev1 = -INFINITY;
    float lsum0 = 0.0f, lsum1 = 0.0f;

    const int rl = lane >> 2, cl2 = (lane & 3) * 2;
    const int row0g = q0 + w * 16 + rl;
    const int row1g = row0g + 8;
    const int brow = wi + ((qq & 2) ? 8 : 0);
    const int bkoff = (qq & 1) ? 16 : 0;
    const int vkr = (lane & 7) + ((lane & 8) ? 8 : 0);
    const int vnoff = (lane & 16) ? 16 : 0;

    for (int jb = 0; jb < nb; ++jb) {
        if (jb < nb - 1) CP_WAIT(1); else CP_WAIT(0);
        __syncthreads();
        if (jb + 2 < nb) { load_kv(jb + 2, (jb + 2) % 3); CP_COMMIT; }
        const uint32_t sb = smb + (uint32_t)(jb % 3) * 24576u;

        // --- S = Q @ K^T (3-pass), scores in log2 domain ---
        float sacc[4][4];
#pragma unroll
        for (int i = 0; i < 4; i++)
#pragma unroll
            for (int v = 0; v < 4; v++) sacc[i][v] = 0.0f;
#pragma unroll
        for (int ks = 0; ks < 8; ks++) {
#pragma unroll
            for (int nt2 = 0; nt2 < 2; nt2++) {
                const uint32_t off = SWZ256((nt2 * 16 + brow) * 256 + ks * 32 + bkoff);
                uint32_t bh[4], bl[4];
                ldsm_x4(bh[0], bh[1], bh[2], bh[3], sb + off);
                ldsm_x4(bl[0], bl[1], bl[2], bl[3], sb + 8192u + off);
                mma_bf16(sacc[nt2 * 2],     qh[ks], bh[0], bh[1]);
                mma_bf16(sacc[nt2 * 2 + 1], qh[ks], bh[2], bh[3]);
                mma_bf16(sacc[nt2 * 2],     qh[ks], bl[0], bl[1]);
                mma_bf16(sacc[nt2 * 2 + 1], qh[ks], bl[2], bl[3]);
                mma_bf16(sacc[nt2 * 2],     ql[ks], bh[0], bh[1]);
                mma_bf16(sacc[nt2 * 2 + 1], ql[ks], bh[2], bh[3]);
            }
        }

        // --- causal mask ---
        if (jb >= 2 * bx) {
            const int kv0 = jb * 32;
#pragma unroll
            for (int nt = 0; nt < 4; nt++) {
                const int c0 = kv0 + nt * 8 + cl2;
                const int c1 = c0 + 1;
                if (c0 > row0g) sacc[nt][0] = -1e30f;
                if (c1 > row0g) sacc[nt][1] = -1e30f;
                if (c0 > row1g) sacc[nt][2] = -1e30f;
                if (c1 > row1g) sacc[nt][3] = -1e30f;
            }
        }

        // --- online softmax (base 2) ---
        float mx0 = -1e30f, mx1 = -1e30f;
#pragma unroll
        for (int nt = 0; nt < 4; nt++) {
            mx0 = fmaxf(mx0, fmaxf(sacc[nt][0], sacc[nt][1]));
            mx1 = fmaxf(mx1, fmaxf(sacc[nt][2], sacc[nt][3]));
        }
        mx0 = fmaxf(mx0, __shfl_xor_sync(0xffffffffu, mx0, 1));
        mx0 = fmaxf(mx0, __shfl_xor_sync(0xffffffffu, mx0, 2));
        mx1 = fmaxf(mx1, __shfl_xor_sync(0xffffffffu, mx1, 1));
        mx1 = fmaxf(mx1, __shfl_xor_sync(0xffffffffu, mx1, 2));
        const float mnew0 = fmaxf(mprev0, mx0);
        const float mnew1 = fmaxf(mprev1, mx1);
        const float alpha0 = exp2f(mprev0 - mnew0);
        const float alpha1 = exp2f(mprev1 - mnew1);
        float rs0 = 0.0f, rs1 = 0.0f;
#pragma unroll
        for (int nt = 0; nt < 4; nt++) {
            sacc[nt][0] = exp2f(sacc[nt][0] - mnew0);
            sacc[nt][1] = exp2f(sacc[nt][1] - mnew0);
            sacc[nt][2] = exp2f(sacc[nt][2] - mnew1);
            sacc[nt][3] = exp2f(sacc[nt][3] - mnew1);
            rs0 += sacc[nt][0] + sacc[nt][1];
            rs1 += sacc[nt][2] + sacc[nt][3];
        }
        rs0 += __shfl_xor_sync(0xffffffffu, rs0, 1);
        rs0 += __shfl_xor_sync(0xffffffffu, rs0, 2);
        rs1 += __shfl_xor_sync(0xffffffffu, rs1, 1);
        rs1 += __shfl_xor_sync(0xffffffffu, rs1, 2);
        lsum0 = lsum0 * alpha0 + rs0;
        lsum1 = lsum1 * alpha1 + rs1;
#pragma unroll
        for (int nt = 0; nt < 16; nt++) {
            oacc[nt][0] *= alpha0; oacc[nt][1] *= alpha0;
            oacc[nt][2] *= alpha1; oacc[nt][3] *= alpha1;
        }
        mprev0 = mnew0; mprev1 = mnew1;

        // --- O += P @ V (single-pass fp16) ---
#pragma unroll
        for (int jp = 0; jp < 2; jp++) {
            uint32_t pf[4];
            pf[0] = pack_f16(sacc[2 * jp][0],     sacc[2 * jp][1]);
            pf[1] = pack_f16(sacc[2 * jp][2],     sacc[2 * jp][3]);
            pf[2] = pack_f16(sacc[2 * jp + 1][0], sacc[2 * jp + 1][1]);
            pf[3] = pack_f16(sacc[2 * jp + 1][2], sacc[2 * jp + 1][3]);
#pragma unroll
            for (int nt2 = 0; nt2 < 8; nt2++) {
                const uint32_t off = SWZ256((jp * 16 + vkr) * 256 + nt2 * 32 + vnoff);
                uint32_t vh[4];
                ldsm_x4_t(vh[0], vh[1], vh[2], vh[3], sb + 16384u + off);
                mma_f16(oacc[nt2 * 2],     pf, vh[0], vh[1]);
                mma_f16(oacc[nt2 * 2 + 1], pf, vh[2], vh[3]);
            }
        }
    }

    // --- epilogue: normalize, fp16 pack, single plane (b*s, h*d) ---
    const float inv0 = 1.0f / lsum0;
    const float inv1 = 1.0f / lsum1;
    const size_t r0 = ((size_t)b * SEQ + row0g) * 2048 + h * 64;
    const size_t r1 = ((size_t)b * SEQ + row1g) * 2048 + h * 64;
#pragma unroll
    for (int nt = 0; nt < 16; nt++) {
        const int d2 = (nt * 8 + cl2) >> 1;
        Of[r0 + d2] = pack_f16(oacc[nt][0] * inv0, oacc[nt][1] * inv0);
        Of[r1 + d2] = pack_f16(oacc[nt][2] * inv1, oacc[nt][3] * inv1);
    }
}

// ---------------------------------------------------------------------------
extern "C" void kernel_launch(void* const* d_in, const int* in_sizes, int n_in,
                              void* d_out, int out_size)
{
    (void)in_sizes; (void)n_in; (void)out_size;
    const float* x     = (const float*)d_in[0];
    const float* freqs = (const float*)d_in[1];
    const float* wq    = (const float*)d_in[3];
    const float* wo    = (const float*)d_in[6];
    const float* ck    = (const float*)d_in[7];
    const float* cv    = (const float*)d_in[8];
    float* out = (float*)d_out;

    void *xhi, *xlo, *wqhi, *wqlo, *wohi, *wolo, *qhi, *qlo, *af;
    void *khi, *klo, *vf;
    cudaGetSymbolAddress(&xhi, g_xhi);   cudaGetSymbolAddress(&xlo, g_xlo);
    cudaGetSymbolAddress(&wqhi, g_wqhi); cudaGetSymbolAddress(&wqlo, g_wqlo);
    cudaGetSymbolAddress(&wohi, g_wohi); cudaGetSymbolAddress(&wolo, g_wolo);
    cudaGetSymbolAddress(&qhi, g_qhi);   cudaGetSymbolAddress(&qlo, g_qlo);
    cudaGetSymbolAddress(&af, g_af);
    cudaGetSymbolAddress(&khi, g_khi);   cudaGetSymbolAddress(&klo, g_klo);
    cudaGetSymbolAddress(&vf, g_vf);

    cudaFuncSetAttribute(gemm_qproj, cudaFuncAttributeMaxDynamicSharedMemorySize, GEMM_SMEM);
    cudaFuncSetAttribute(gemm_oproj, cudaFuncAttributeMaxDynamicSharedMemorySize, GEMM2_SMEM);
    cudaFuncSetAttribute(attn_tc, cudaFuncAttributeMaxDynamicSharedMemorySize, ATT_SMEM);

    dim3 blk(256);
    conv3<<<dim3(2048, 3), blk>>>(
        (const float4*)x, (const float4*)wq, (const float4*)wo,
        (uint2*)xhi, (uint2*)xlo, (uint2*)wqhi, (uint2*)wqlo,
        (uint2*)wohi, (uint2*)wolo);
    conv_kv4<<<dim3(1024, 2), blk>>>(
        (const float4*)ck, (const float4*)cv,
        (uint2*)khi, (uint2*)klo, (uint2*)vf);

    gemm_qproj<<<dim3(32, 32), blk, GEMM_SMEM>>>(
        (const uint32_t*)xhi, (const uint32_t*)xlo,
        (const uint32_t*)wqhi, (const uint32_t*)wqlo,
        freqs, (uint32_t*)qhi, (uint32_t*)qlo);

    attn_tc<<<dim3(32, 64), dim3(128), ATT_SMEM>>>(
        (const uint32_t*)qhi, (const uint32_t*)qlo,
        (const uint32_t*)khi, (const uint32_t*)klo,
        (const uint32_t*)vf,
        (uint32_t*)af);

    gemm_oproj<<<dim3(32, 32), blk, GEMM2_SMEM>>>(
        (const uint32_t*)af,
        (const uint32_t*)wohi, (const uint32_t*)wolo,
        out);
}

// round 14
// speedup vs baseline: 1.4652x; 1.1743x over previous
#include <cuda_runtime.h>
#include <cuda_bf16.h>
#include <cuda_fp16.h>
#include <math.h>
#include <stdint.h>

#define BATCH 2
#define SEQ   2048
#define DMODEL 4096
#define NHEADS 32
#define NKVH  8
#define HEADD 128
#define KVLEN 2048

// QSCALE * log2(e): softmax done in base-2
#define QSC2 (0.08838834764831845f * 1.4426950408889634f)

// ---------------------------------------------------------------------------
// Global scratch.
// x: fp16 hi/lo planes. wq: single fp16 plane. wo: fp16 hi/lo planes.
// q: bf16 hi/lo. K: bf16 hi/lo. V: fp16. attn out: single fp16 plane.
// ---------------------------------------------------------------------------
#define PLANE_U32 (8388608)
__device__ uint32_t g_xhi[PLANE_U32],  g_xlo[PLANE_U32];   // x (b*s, k) fp16 hi/lo
__device__ uint32_t g_wqf[PLANE_U32];                      // wq (n, k) fp16
__device__ uint32_t g_wohi[PLANE_U32], g_wolo[PLANE_U32];  // wo (n, k) fp16 hi/lo
__device__ uint32_t g_qhi[PLANE_U32],  g_qlo[PLANE_U32];   // q (b,h,s,d) bf16
__device__ uint32_t g_af[PLANE_U32];                       // attn out (b*s, h*d) fp16
#define KV_U32 (2097152)
__device__ uint32_t g_khi[KV_U32], g_klo[KV_U32];          // (b,g,s,d) bf16 hi/lo
__device__ uint32_t g_vf[KV_U32];                          // (b,g,s,d) fp16x2

// ---------------------------------------------------------------------------
__device__ __forceinline__ uint32_t smem_to_u32(const void* p) {
    uint32_t a;
    asm("{ .reg .u64 t; cvta.to.shared.u64 t, %1; cvt.u32.u64 %0, t; }" : "=r"(a) : "l"(p));
    return a;
}
#define SWZ64(off)  ((uint32_t)(off) ^ ((((uint32_t)(off)) >> 3) & 0x30u))
#define SWZ256(off) ((uint32_t)(off) ^ ((((uint32_t)(off)) >> 4) & 0x70u))

__device__ __forceinline__ void cp16(uint32_t dst, const void* src) {
    asm volatile("cp.async.cg.shared.global [%0], [%1], 16;" :: "r"(dst), "l"(src));
}
#define CP_COMMIT asm volatile("cp.async.commit_group;" ::: "memory")
#define CP_WAIT(n) asm volatile("cp.async.wait_group %0;" :: "n"(n) : "memory")

__device__ __forceinline__ void ldsm_x4(uint32_t& r0, uint32_t& r1, uint32_t& r2, uint32_t& r3,
                                        uint32_t addr) {
    asm volatile("ldmatrix.sync.aligned.m8n8.x4.shared.b16 {%0,%1,%2,%3}, [%4];"
                 : "=r"(r0), "=r"(r1), "=r"(r2), "=r"(r3) : "r"(addr));
}
__device__ __forceinline__ void ldsm_x4_t(uint32_t& r0, uint32_t& r1, uint32_t& r2, uint32_t& r3,
                                          uint32_t addr) {
    asm volatile("ldmatrix.sync.aligned.m8n8.x4.trans.shared.b16 {%0,%1,%2,%3}, [%4];"
                 : "=r"(r0), "=r"(r1), "=r"(r2), "=r"(r3) : "r"(addr));
}
__device__ __forceinline__ void mma_bf16(float* d, const uint32_t* a, uint32_t b0, uint32_t b1) {
    asm volatile(
        "mma.sync.aligned.m16n8k16.row.col.f32.bf16.bf16.f32 "
        "{%0,%1,%2,%3}, {%4,%5,%6,%7}, {%8,%9}, {%0,%1,%2,%3};"
        : "+f"(d[0]), "+f"(d[1]), "+f"(d[2]), "+f"(d[3])
        : "r"(a[0]), "r"(a[1]), "r"(a[2]), "r"(a[3]), "r"(b0), "r"(b1));
}
__device__ __forceinline__ void mma_f16(float* d, const uint32_t* a, uint32_t b0, uint32_t b1) {
    asm volatile(
        "mma.sync.aligned.m16n8k16.row.col.f32.f16.f16.f32 "
        "{%0,%1,%2,%3}, {%4,%5,%6,%7}, {%8,%9}, {%0,%1,%2,%3};"
        : "+f"(d[0]), "+f"(d[1]), "+f"(d[2]), "+f"(d[3])
        : "r"(a[0]), "r"(a[1]), "r"(a[2]), "r"(a[3]), "r"(b0), "r"(b1));
}
__device__ __forceinline__ void pack_hilo(float a, float b, uint32_t& hi, uint32_t& lo) {
    uint32_t h;
    asm("cvt.rn.bf16x2.f32 %0, %1, %2;" : "=r"(h) : "f"(b), "f"(a));
    float fa = __uint_as_float(h << 16);
    float fb = __uint_as_float(h & 0xffff0000u);
    float ra = a - fa;
    float rb = b - fb;
    uint32_t l;
    asm("cvt.rn.bf16x2.f32 %0, %1, %2;" : "=r"(l) : "f"(rb), "f"(ra));
    hi = h; lo = l;
}
__device__ __forceinline__ uint32_t pack_f16(float a, float b) {
    __half2 h = __floats2half2_rn(a, b);
    return *(uint32_t*)&h;
}
__device__ __forceinline__ void pack_f16_hilo(float a, float b, uint32_t& hi, uint32_t& lo) {
    __half2 h = __floats2half2_rn(a, b);
    float2 hf = __half22float2(h);
    __half2 l = __floats2half2_rn(a - hf.x, b - hf.y);
    hi = *(uint32_t*)&h;
    lo = *(uint32_t*)&l;
}

// ---------------------------------------------------------------------------
// Conversion kernels
// ---------------------------------------------------------------------------
// y=0: x -> fp16 hi/lo. y=1: wq -> fp16 single. y=2: wo -> fp16 hi/lo.
__global__ void conv3(const float4* __restrict__ s0, const float4* __restrict__ s1,
                      const float4* __restrict__ s2,
                      uint2* xh, uint2* xl, uint2* wqf, uint2* wh, uint2* wl)
{
    const int mode = blockIdx.y;
    const float4* src = (mode == 0) ? s0 : (mode == 1) ? s1 : s2;
    const int n4 = PLANE_U32 / 2;
    for (int i = blockIdx.x * blockDim.x + threadIdx.x; i < n4;
         i += gridDim.x * blockDim.x) {
        float4 v = src[i];
        if (mode == 1) {
            wqf[i] = make_uint2(pack_f16(v.x, v.y), pack_f16(v.z, v.w));
        } else {
            uint32_t ha, la, hb, lb;
            pack_f16_hilo(v.x, v.y, ha, la);
            pack_f16_hilo(v.z, v.w, hb, lb);
            uint2* hi = (mode == 0) ? xh : wh;
            uint2* lo = (mode == 0) ? xl : wl;
            hi[i] = make_uint2(ha, hb);
            lo[i] = make_uint2(la, lb);
        }
    }
}

// K: (b,s,g,d) fp32 -> bf16 hi/lo planes (b,g,s,d).  V: -> fp16x2 plane.
__global__ void conv_kv4(const float4* __restrict__ ksrc, const float4* __restrict__ vsrc,
                         uint2* kh, uint2* kl, uint2* vf)
{
    const int isV = blockIdx.y;
    const float4* src = isV ? vsrc : ksrc;
    const int n4 = KV_U32 / 2;
    for (int p = blockIdx.x * blockDim.x + threadIdx.x; p < n4;
         p += gridDim.x * blockDim.x) {
        const int d4 = p & 31;
        const int s = (p >> 5) & 2047;
        const int g = (p >> 16) & 7;
        const int b = p >> 19;
        float4 v = src[(((size_t)b * SEQ + s) * NKVH + g) * 32 + d4];
        if (isV) {
            vf[p] = make_uint2(pack_f16(v.x, v.y), pack_f16(v.z, v.w));
        } else {
            uint32_t ha, la, hb, lb;
            pack_hilo(v.x, v.y, ha, la);
            pack_hilo(v.z, v.w, hb, lb);
            kh[p] = make_uint2(ha, hb);
            kl[p] = make_uint2(la, lb);
        }
    }
}

// ---------------------------------------------------------------------------
// 2-pass fp16 GEMM, Q projection: Q = (Xhi + Xlo) @ Wf^T.
// A fp16 hi/lo planes; B single fp16 plane. CTA 128x128, 8 warps (32x64),
// K-chunk 32, 3 x 24KB stages (Ahi 8K | Alo 8K | Bf 8K), 2 CTAs/SM.
// Epilogue: freqs * QSC2 -> bf16 hi/lo Qh/Ql (b,h,s,d).
// ---------------------------------------------------------------------------
#define GEMMQ_SMEM (3 * 24576)

__global__ __launch_bounds__(256, 2) void gemm_qproj2(
    const uint32_t* __restrict__ Ahi, const uint32_t* __restrict__ Alo,
    const uint32_t* __restrict__ Bf,
    const float* __restrict__ freqs,
    uint32_t* __restrict__ Qh, uint32_t* __restrict__ Ql)
{
    extern __shared__ char sm[];
    const uint32_t smb = smem_to_u32(sm);
    const int tid = threadIdx.x;
    const int wid = tid >> 5;
    const int lane = tid & 31;
    const int wn = wid & 1;
    const int wm = wid >> 1;
    const int m0 = blockIdx.y * 128;
    const int n0 = blockIdx.x * 128;

    float acc[2][8][4];
#pragma unroll
    for (int i = 0; i < 2; i++)
#pragma unroll
        for (int j = 0; j < 8; j++)
#pragma unroll
            for (int v = 0; v < 4; v++) acc[i][j][v] = 0.0f;

    auto load_stage = [&](int ch, int st) {
        const uint32_t sbase = smb + (uint32_t)st * 24576u;
        const int kc2 = ch * 16;
#pragma unroll
        for (int t = tid; t < 1536; t += 256) {
            const int plane = t >> 9;            // Ahi Alo Bf
            const int i = t & 511;
            const int row = i >> 2, ck = i & 3;
            const uint32_t dst = sbase + plane * 8192u + SWZ64(row * 64 + ck * 16);
            const uint32_t* bp = (plane == 0) ? Ahi : (plane == 1) ? Alo : Bf;
            const int r0 = (plane < 2) ? m0 : n0;
            cp16(dst, bp + (size_t)(r0 + row) * 2048 + kc2 + ck * 4);
        }
    };

    const int q = lane >> 3;
    const int wi = lane & 7;
    const int arow_base = wm * 32 + wi + ((q & 1) ? 8 : 0);
    const int akb_off = (q & 2) ? 16 : 0;
    const int brow_base = wn * 64 + wi + ((q & 2) ? 8 : 0);
    const int bkb_off = (q & 1) ? 16 : 0;

    load_stage(0, 0); CP_COMMIT;
    load_stage(1, 1); CP_COMMIT;

    for (int ch = 0; ch < 128; ++ch) {
        if (ch < 127) CP_WAIT(1); else CP_WAIT(0);
        __syncthreads();
        if (ch + 2 < 128) { load_stage(ch + 2, (ch + 2) % 3); CP_COMMIT; }

        const uint32_t sbase = smb + (uint32_t)(ch % 3) * 24576u;
        const uint32_t pAhi = sbase, pAlo = sbase + 8192u, pBf = sbase + 16384u;

#pragma unroll
        for (int ks = 0; ks < 2; ++ks) {
            const int kb0 = ks * 32;
            uint32_t ah[2][4], al[2][4];
#pragma unroll
            for (int mt = 0; mt < 2; ++mt) {
                const int r = arow_base + mt * 16;
                const uint32_t off = SWZ64(r * 64 + kb0 + akb_off);
                ldsm_x4(ah[mt][0], ah[mt][1], ah[mt][2], ah[mt][3], pAhi + off);
                ldsm_x4(al[mt][0], al[mt][1], al[mt][2], al[mt][3], pAlo + off);
            }
#pragma unroll
            for (int np = 0; np < 4; ++np) {
                const int rn = brow_base + np * 16;
                const uint32_t offb = SWZ64(rn * 64 + kb0 + bkb_off);
                uint32_t bf[4];
                ldsm_x4(bf[0], bf[1], bf[2], bf[3], pBf + offb);
#pragma unroll
                for (int mt = 0; mt < 2; ++mt) {
                    mma_f16(acc[mt][np * 2],     ah[mt], bf[0], bf[1]);
                    mma_f16(acc[mt][np * 2 + 1], ah[mt], bf[2], bf[3]);
                    mma_f16(acc[mt][np * 2],     al[mt], bf[0], bf[1]);
                    mma_f16(acc[mt][np * 2 + 1], al[mt], bf[2], bf[3]);
                }
            }
        }
    }

    const int rl = lane >> 2;
    const int cl = (lane & 3) * 2;
#pragma unroll
    for (int mt = 0; mt < 2; ++mt) {
#pragma unroll
        for (int nn = 0; nn < 8; ++nn) {
            const int r = m0 + wm * 32 + mt * 16 + rl;
            const int c = n0 + wn * 64 + nn * 8 + cl;
#pragma unroll
            for (int half = 0; half < 2; ++half) {
                const int rr = r + half * 8;
                const float v0 = acc[mt][nn][half * 2];
                const float v1 = acc[mt][nn][half * 2 + 1];
                const int b = rr >> 11;
                const int s = rr & (SEQ - 1);
                const int h = c >> 7;
                const int d = c & (HEADD - 1);
                float2 f = *(const float2*)&freqs[(size_t)s * 64 + (d & 63)];
                uint32_t hi, lo;
                pack_hilo(v0 * f.x * QSC2, v1 * f.y * QSC2, hi, lo);
                const size_t idx = (((size_t)b * NHEADS + h) * SEQ + s) * 64 + (d >> 1);
                Qh[idx] = hi; Ql[idx] = lo;
            }
        }
    }
}

// ---------------------------------------------------------------------------
// 2-pass fp16 GEMM, O projection: C = Af @ (Wh + Wl)^T. (proven R13 config)
// Stages: 3 x 24KB (Af 8K | Bhi 8K | Blo 8K). 2 CTAs/SM.
// ---------------------------------------------------------------------------
#define GEMM2_SMEM (3 * 24576)

__global__ __launch_bounds__(256, 2) void gemm_oproj(
    const uint32_t* __restrict__ Af,
    const uint32_t* __restrict__ Bhi, const uint32_t* __restrict__ Blo,
    float* __restrict__ C)
{
    extern __shared__ char sm[];
    const uint32_t smb = smem_to_u32(sm);
    const int tid = threadIdx.x;
    const int wid = tid >> 5;
    const int lane = tid & 31;
    const int wn = wid & 1;
    const int wm = wid >> 1;
    const int m0 = blockIdx.y * 128;
    const int n0 = blockIdx.x * 128;

    float acc[2][8][4];
#pragma unroll
    for (int i = 0; i < 2; i++)
#pragma unroll
        for (int j = 0; j < 8; j++)
#pragma unroll
            for (int v = 0; v < 4; v++) acc[i][j][v] = 0.0f;

    auto load_stage = [&](int ch, int st) {
        const uint32_t sbase = smb + (uint32_t)st * 24576u;
        const int kc2 = ch * 16;
#pragma unroll
        for (int t = tid; t < 1536; t += 256) {
            const int plane = t >> 9;            // Af Bhi Blo
            const int i = t & 511;
            const int row = i >> 2, ck = i & 3;
            const uint32_t dst = sbase + plane * 8192u + SWZ64(row * 64 + ck * 16);
            const uint32_t* bp = (plane == 0) ? Af : (plane == 1) ? Bhi : Blo;
            const int r0 = (plane == 0) ? m0 : n0;
            cp16(dst, bp + (size_t)(r0 + row) * 2048 + kc2 + ck * 4);
        }
    };

    const int q = lane >> 3;
    const int wi = lane & 7;
    const int arow_base = wm * 32 + wi + ((q & 1) ? 8 : 0);
    const int akb_off = (q & 2) ? 16 : 0;
    const int brow_base = wn * 64 + wi + ((q & 2) ? 8 : 0);
    const int bkb_off = (q & 1) ? 16 : 0;

    load_stage(0, 0); CP_COMMIT;
    load_stage(1, 1); CP_COMMIT;

    for (int ch = 0; ch < 128; ++ch) {
        if (ch < 127) CP_WAIT(1); else CP_WAIT(0);
        __syncthreads();
        if (ch + 2 < 128) { load_stage(ch + 2, (ch + 2) % 3); CP_COMMIT; }

        const uint32_t sbase = smb + (uint32_t)(ch % 3) * 24576u;
        const uint32_t pAf = sbase;
        const uint32_t pBhi = sbase + 8192u, pBlo = sbase + 16384u;

#pragma unroll
        for (int ks = 0; ks < 2; ++ks) {
            const int kb0 = ks * 32;
            uint32_t af[2][4];
#pragma unroll
            for (int mt = 0; mt < 2; ++mt) {
                const int r = arow_base + mt * 16;
                const uint32_t off = SWZ64(r * 64 + kb0 + akb_off);
                ldsm_x4(af[mt][0], af[mt][1], af[mt][2], af[mt][3], pAf + off);
            }
#pragma unroll
            for (int np = 0; np < 4; ++np) {
                const int rn = brow_base + np * 16;
                const uint32_t offb = SWZ64(rn * 64 + kb0 + bkb_off);
                uint32_t bh[4], bl[4];
                ldsm_x4(bh[0], bh[1], bh[2], bh[3], pBhi + offb);
                ldsm_x4(bl[0], bl[1], bl[2], bl[3], pBlo + offb);
#pragma unroll
                for (int mt = 0; mt < 2; ++mt) {
                    mma_f16(acc[mt][np * 2],     af[mt], bh[0], bh[1]);
                    mma_f16(acc[mt][np * 2 + 1], af[mt], bh[2], bh[3]);
                    mma_f16(acc[mt][np * 2],     af[mt], bl[0], bl[1]);
                    mma_f16(acc[mt][np * 2 + 1], af[mt], bl[2], bl[3]);
                }
            }
        }
    }

    const int rl = lane >> 2;
    const int cl = (lane & 3) * 2;
#pragma unroll
    for (int mt = 0; mt < 2; ++mt) {
#pragma unroll
        for (int nn = 0; nn < 8; ++nn) {
            const int r = m0 + wm * 32 + mt * 16 + rl;
            const int c = n0 + wn * 64 + nn * 8 + cl;
#pragma unroll
            for (int half = 0; half < 2; ++half) {
                const int rr = r + half * 8;
                *(float2*)&C[(size_t)rr * DMODEL + c] =
                    make_float2(acc[mt][nn][half * 2], acc[mt][nn][half * 2 + 1]);
            }
        }
    }
}

// ---------------------------------------------------------------------------
// Tensor-core flash attention (causal). S = bf16 hi/lo 3-pass (base-2 softmax);
// PV = single-pass fp16. Output -> single fp16 plane. (proven R13 config)
// ---------------------------------------------------------------------------
#define ATT_QOFF 73728u
#define ATT_SMEM (73728 + 32768)

__global__ __launch_bounds__(128, 2) void attn_tc(
    const uint32_t* __restrict__ Qhi, const uint32_t* __restrict__ Qlo,
    const uint32_t* __restrict__ Khi, const uint32_t* __restrict__ Klo,
    const uint32_t* __restrict__ Vf,
    uint32_t* __restrict__ Of)
{
    extern __shared__ char sm[];
    const uint32_t smb = smem_to_u32(sm);
    const int tid = threadIdx.x;
    const int w = tid >> 5;
    const int lane = tid & 31;
    const int bx = gridDim.x - 1 - blockIdx.x;   // big tiles first
    const int by = blockIdx.y;
    const int b = by >> 5, h = by & 31, g = h >> 2;
    const int q0 = bx * 64;
    const int nb = 2 * bx + 2;                   // KV blocks of 32 rows

    const size_t qbase = (((size_t)b * NHEADS + h) * SEQ + q0) * 64;
#pragma unroll
    for (int t = tid; t < 2048; t += 128) {
        const int plane = t >> 10;
        const int i = t & 1023;
        const int row = i >> 4, ck = i & 15;
        const uint32_t dst = smb + ATT_QOFF + plane * 16384u + SWZ256(row * 256 + ck * 16);
        cp16(dst, (plane ? Qlo : Qhi) + qbase + (size_t)row * 64 + ck * 4);
    }
    CP_COMMIT;

    const size_t kvbase = ((size_t)b * NKVH + g) * KVLEN * 64;
    auto load_kv = [&](int jb, int region) {
        const uint32_t sb = smb + (uint32_t)region * 24576u;
        const int kv0 = jb * 32;
#pragma unroll
        for (int t = tid; t < 1536; t += 128) {
            const int plane = t >> 9;                 // Khi Klo Vf
            const int i = t & 511;
            const int row = i >> 4, ck = i & 15;
            const uint32_t dst = sb + plane * 8192u + SWZ256(row * 256 + ck * 16);
            const uint32_t* base = (plane == 0) ? Khi : (plane == 1) ? Klo : Vf;
            cp16(dst, base + kvbase + (size_t)(kv0 + row) * 64 + ck * 4);
        }
    };

    load_kv(0, 0); CP_COMMIT;
    load_kv(1, 1); CP_COMMIT;
    CP_WAIT(2);                 // Q done
    __syncthreads();

    const int wi = lane & 7, qq = lane >> 3;
    const int arow = w * 16 + wi + ((qq & 1) ? 8 : 0);
    const int akoff = (qq & 2) ? 16 : 0;
    uint32_t qh[8][4], ql[8][4];
#pragma unroll
    for (int ks = 0; ks < 8; ks++) {
        const uint32_t off = SWZ256(arow * 256 + ks * 32 + akoff);
        ldsm_x4(qh[ks][0], qh[ks][1], qh[ks][2], qh[ks][3], smb + ATT_QOFF + off);
        ldsm_x4(ql[ks][0], ql[ks][1], ql[ks][2], ql[ks][3], smb + ATT_QOFF + 16384u + off);
    }

    float oacc[16][4];
#pragma unroll
    for (int i = 0; i < 16; i++)
#pragma unroll
        for (int v = 0; v < 4; v++) oacc[i][v] = 0.0f;
    float mprev0 = -INFINITY, mprev1 = -INFINITY;
    float lsum0 = 0.0f, lsum1 = 0.0f;

    const int rl = lane >> 2, cl2 = (lane & 3) * 2;
    const int row0g = q0 + w * 16 + rl;
    const int row1g = row0g + 8;
    const int brow = wi + ((qq & 2) ? 8 : 0);
    const int bkoff = (qq & 1) ? 16 : 0;
    const int vkr = (lane & 7) + ((lane & 8) ? 8 : 0);
    const int vnoff = (lane & 16) ? 16 : 0;

    for (int jb = 0; jb < nb; ++jb) {
        if (jb < nb - 1) CP_WAIT(1); else CP_WAIT(0);
        __syncthreads();
        if (jb + 2 < nb) { load_kv(jb + 2, (jb + 2) % 3); CP_COMMIT; }
        const uint32_t sb = smb + (uint32_t)(jb % 3) * 24576u;

        float sacc[4][4];
#pragma unroll
        for (int i = 0; i < 4; i++)
#pragma unroll
            for (int v = 0; v < 4; v++) sacc[i][v] = 0.0f;
#pragma unroll
        for (int ks = 0; ks < 8; ks++) {
#pragma unroll
            for (int nt2 = 0; nt2 < 2; nt2++) {
                const uint32_t off = SWZ256((nt2 * 16 + brow) * 256 + ks * 32 + bkoff);
                uint32_t bh[4], bl[4];
                ldsm_x4(bh[0], bh[1], bh[2], bh[3], sb + off);
                ldsm_x4(bl[0], bl[1], bl[2], bl[3], sb + 8192u + off);
                mma_bf16(sacc[nt2 * 2],     qh[ks], bh[0], bh[1]);
                mma_bf16(sacc[nt2 * 2 + 1], qh[ks], bh[2], bh[3]);
                mma_bf16(sacc[nt2 * 2],     qh[ks], bl[0], bl[1]);
                mma_bf16(sacc[nt2 * 2 + 1], qh[ks], bl[2], bl[3]);
                mma_bf16(sacc[nt2 * 2],     ql[ks], bh[0], bh[1]);
                mma_bf16(sacc[nt2 * 2 + 1], ql[ks], bh[2], bh[3]);
            }
        }

        if (jb >= 2 * bx) {
            const int kv0 = jb * 32;
#pragma unroll
            for (int nt = 0; nt < 4; nt++) {
                const int c0 = kv0 + nt * 8 + cl2;
                const int c1 = c0 + 1;
                if (c0 > row0g) sacc[nt][0] = -1e30f;
                if (c1 > row0g) sacc[nt][1] = -1e30f;
                if (c0 > row1g) sacc[nt][2] = -1e30f;
                if (c1 > row1g) sacc[nt][3] = -1e30f;
            }
        }

        float mx0 = -1e30f, mx1 = -1e30f;
#pragma unroll
        for (int nt = 0; nt < 4; nt++) {
            mx0 = fmaxf(mx0, fmaxf(sacc[nt][0], sacc[nt][1]));
            mx1 = fmaxf(mx1, fmaxf(sacc[nt][2], sacc[nt][3]));
        }
        mx0 = fmaxf(mx0, __shfl_xor_sync(0xffffffffu, mx0, 1));
        mx0 = fmaxf(mx0, __shfl_xor_sync(0xffffffffu, mx0, 2));
        mx1 = fmaxf(mx1, __shfl_xor_sync(0xffffffffu, mx1, 1));
        mx1 = fmaxf(mx1, __shfl_xor_sync(0xffffffffu, mx1, 2));
        const float mnew0 = fmaxf(mprev0, mx0);
        const float mnew1 = fmaxf(mprev1, mx1);
        const float alpha0 = exp2f(mprev0 - mnew0);
        const float alpha1 = exp2f(mprev1 - mnew1);
        float rs0 = 0.0f, rs1 = 0.0f;
#pragma unroll
        for (int nt = 0; nt < 4; nt++) {
            sacc[nt][0] = exp2f(sacc[nt][0] - mnew0);
            sacc[nt][1] = exp2f(sacc[nt][1] - mnew0);
            sacc[nt][2] = exp2f(sacc[nt][2] - mnew1);
            sacc[nt][3] = exp2f(sacc[nt][3] - mnew1);
            rs0 += sacc[nt][0] + sacc[nt][1];
            rs1 += sacc[nt][2] + sacc[nt][3];
        }
        rs0 += __shfl_xor_sync(0xffffffffu, rs0, 1);
        rs0 += __shfl_xor_sync(0xffffffffu, rs0, 2);
        rs1 += __shfl_xor_sync(0xffffffffu, rs1, 1);
        rs1 += __shfl_xor_sync(0xffffffffu, rs1, 2);
        lsum0 = lsum0 * alpha0 + rs0;
        lsum1 = lsum1 * alpha1 + rs1;
#pragma unroll
        for (int nt = 0; nt < 16; nt++) {
            oacc[nt][0] *= alpha0; oacc[nt][1] *= alpha0;
            oacc[nt][2] *= alpha1; oacc[nt][3] *= alpha1;
        }
        mprev0 = mnew0; mprev1 = mnew1;

#pragma unroll
        for (int jp = 0; jp < 2; jp++) {
            uint32_t pf[4];
            pf[0] = pack_f16(sacc[2 * jp][0],     sacc[2 * jp][1]);
            pf[1] = pack_f16(sacc[2 * jp][2],     sacc[2 * jp][3]);
            pf[2] = pack_f16(sacc[2 * jp + 1][0], sacc[2 * jp + 1][1]);
            pf[3] = pack_f16(sacc[2 * jp + 1][2], sacc[2 * jp + 1][3]);
#pragma unroll
            for (int nt2 = 0; nt2 < 8; nt2++) {
                const uint32_t off = SWZ256((jp * 16 + vkr) * 256 + nt2 * 32 + vnoff);
                uint32_t vh[4];
                ldsm_x4_t(vh[0], vh[1], vh[2], vh[3], sb + 16384u + off);
                mma_f16(oacc[nt2 * 2],     pf, vh[0], vh[1]);
                mma_f16(oacc[nt2 * 2 + 1], pf, vh[2], vh[3]);
            }
        }
    }

    const float inv0 = 1.0f / lsum0;
    const float inv1 = 1.0f / lsum1;
    const size_t r0 = ((size_t)b * SEQ + row0g) * 2048 + h * 64;
    const size_t r1 = ((size_t)b * SEQ + row1g) * 2048 + h * 64;
#pragma unroll
    for (int nt = 0; nt < 16; nt++) {
        const int d2 = (nt * 8 + cl2) >> 1;
        Of[r0 + d2] = pack_f16(oacc[nt][0] * inv0, oacc[nt][1] * inv0);
        Of[r1 + d2] = pack_f16(oacc[nt][2] * inv1, oacc[nt][3] * inv1);
    }
}

// ---------------------------------------------------------------------------
extern "C" void kernel_launch(void* const* d_in, const int* in_sizes, int n_in,
                              void* d_out, int out_size)
{
    (void)in_sizes; (void)n_in; (void)out_size;
    const float* x     = (const float*)d_in[0];
    const float* freqs = (const float*)d_in[1];
    const float* wq    = (const float*)d_in[3];
    const float* wo    = (const float*)d_in[6];
    const float* ck    = (const float*)d_in[7];
    const float* cv    = (const float*)d_in[8];
    float* out = (float*)d_out;

    void *xhi, *xlo, *wqf, *wohi, *wolo, *qhi, *qlo, *af;
    void *khi, *klo, *vf;
    cudaGetSymbolAddress(&xhi, g_xhi);   cudaGetSymbolAddress(&xlo, g_xlo);
    cudaGetSymbolAddress(&wqf, g_wqf);
    cudaGetSymbolAddress(&wohi, g_wohi); cudaGetSymbolAddress(&wolo, g_wolo);
    cudaGetSymbolAddress(&qhi, g_qhi);   cudaGetSymbolAddress(&qlo, g_qlo);
    cudaGetSymbolAddress(&af, g_af);
    cudaGetSymbolAddress(&khi, g_khi);   cudaGetSymbolAddress(&klo, g_klo);
    cudaGetSymbolAddress(&vf, g_vf);

    cudaFuncSetAttribute(gemm_qproj2, cudaFuncAttributeMaxDynamicSharedMemorySize, GEMMQ_SMEM);
    cudaFuncSetAttribute(gemm_oproj, cudaFuncAttributeMaxDynamicSharedMemorySize, GEMM2_SMEM);
    cudaFuncSetAttribute(attn_tc, cudaFuncAttributeMaxDynamicSharedMemorySize, ATT_SMEM);

    dim3 blk(256);
    conv3<<<dim3(2048, 3), blk>>>(
        (const float4*)x, (const float4*)wq, (const float4*)wo,
        (uint2*)xhi, (uint2*)xlo, (uint2*)wqf, (uint2*)wohi, (uint2*)wolo);
    conv_kv4<<<dim3(1024, 2), blk>>>(
        (const float4*)ck, (const float4*)cv,
        (uint2*)khi, (uint2*)klo, (uint2*)vf);

    gemm_qproj2<<<dim3(32, 32), blk, GEMMQ_SMEM>>>(
        (const uint32_t*)xhi, (const uint32_t*)xlo,
        (const uint32_t*)wqf,
        freqs, (uint32_t*)qhi, (uint32_t*)qlo);

    attn_tc<<<dim3(32, 64), dim3(128), ATT_SMEM>>>(
        (const uint32_t*)qhi, (const uint32_t*)qlo,
        (const uint32_t*)khi, (const uint32_t*)klo,
        (const uint32_t*)vf,
        (uint32_t*)af);

    gemm_oproj<<<dim3(32, 32), blk, GEMM2_SMEM>>>(
        (const uint32_t*)af,
        (const uint32_t*)wohi, (const uint32_t*)wolo,
        out);
}

// round 15
// speedup vs baseline: 2.1208x; 1.4475x over previous
#include <cuda_runtime.h>
#include <cuda_bf16.h>
#include <cuda_fp16.h>
#include <math.h>
#include <stdint.h>

#define BATCH 2
#define SEQ   2048
#define DMODEL 4096
#define NHEADS 32
#define NKVH  8
#define HEADD 128
#define KVLEN 2048

// QSCALE * log2(e): softmax done in base-2
#define QSC2 (0.08838834764831845f * 1.4426950408889634f)

// ---------------------------------------------------------------------------
// Global scratch.
// x/wq/wo: single fp16 planes. q: bf16 hi/lo. K: bf16 hi/lo. V: fp16.
// attn out: single fp16 plane.
// ---------------------------------------------------------------------------
#define PLANE_U32 (8388608)
__device__ uint32_t g_xf[PLANE_U32];                       // x (b*s, k) fp16
__device__ uint32_t g_wqf[PLANE_U32];                      // wq (n, k) fp16
__device__ uint32_t g_wof[PLANE_U32];                      // wo (n, k) fp16
__device__ uint32_t g_qhi[PLANE_U32],  g_qlo[PLANE_U32];   // q (b,h,s,d) bf16
__device__ uint32_t g_af[PLANE_U32];                       // attn out (b*s, h*d) fp16
#define KV_U32 (2097152)
__device__ uint32_t g_khi[KV_U32], g_klo[KV_U32];          // (b,g,s,d) bf16 hi/lo
__device__ uint32_t g_vf[KV_U32];                          // (b,g,s,d) fp16x2

// ---------------------------------------------------------------------------
__device__ __forceinline__ uint32_t smem_to_u32(const void* p) {
    uint32_t a;
    asm("{ .reg .u64 t; cvta.to.shared.u64 t, %1; cvt.u32.u64 %0, t; }" : "=r"(a) : "l"(p));
    return a;
}
#define SWZ64(off)  ((uint32_t)(off) ^ ((((uint32_t)(off)) >> 3) & 0x30u))
#define SWZ256(off) ((uint32_t)(off) ^ ((((uint32_t)(off)) >> 4) & 0x70u))

__device__ __forceinline__ void cp16(uint32_t dst, const void* src) {
    asm volatile("cp.async.cg.shared.global [%0], [%1], 16;" :: "r"(dst), "l"(src));
}
#define CP_COMMIT asm volatile("cp.async.commit_group;" ::: "memory")
#define CP_WAIT(n) asm volatile("cp.async.wait_group %0;" :: "n"(n) : "memory")

__device__ __forceinline__ void ldsm_x4(uint32_t& r0, uint32_t& r1, uint32_t& r2, uint32_t& r3,
                                        uint32_t addr) {
    asm volatile("ldmatrix.sync.aligned.m8n8.x4.shared.b16 {%0,%1,%2,%3}, [%4];"
                 : "=r"(r0), "=r"(r1), "=r"(r2), "=r"(r3) : "r"(addr));
}
__device__ __forceinline__ void ldsm_x4_t(uint32_t& r0, uint32_t& r1, uint32_t& r2, uint32_t& r3,
                                          uint32_t addr) {
    asm volatile("ldmatrix.sync.aligned.m8n8.x4.trans.shared.b16 {%0,%1,%2,%3}, [%4];"
                 : "=r"(r0), "=r"(r1), "=r"(r2), "=r"(r3) : "r"(addr));
}
__device__ __forceinline__ void mma_bf16(float* d, const uint32_t* a, uint32_t b0, uint32_t b1) {
    asm volatile(
        "mma.sync.aligned.m16n8k16.row.col.f32.bf16.bf16.f32 "
        "{%0,%1,%2,%3}, {%4,%5,%6,%7}, {%8,%9}, {%0,%1,%2,%3};"
        : "+f"(d[0]), "+f"(d[1]), "+f"(d[2]), "+f"(d[3])
        : "r"(a[0]), "r"(a[1]), "r"(a[2]), "r"(a[3]), "r"(b0), "r"(b1));
}
__device__ __forceinline__ void mma_f16(float* d, const uint32_t* a, uint32_t b0, uint32_t b1) {
    asm volatile(
        "mma.sync.aligned.m16n8k16.row.col.f32.f16.f16.f32 "
        "{%0,%1,%2,%3}, {%4,%5,%6,%7}, {%8,%9}, {%0,%1,%2,%3};"
        : "+f"(d[0]), "+f"(d[1]), "+f"(d[2]), "+f"(d[3])
        : "r"(a[0]), "r"(a[1]), "r"(a[2]), "r"(a[3]), "r"(b0), "r"(b1));
}
__device__ __forceinline__ void pack_hilo(float a, float b, uint32_t& hi, uint32_t& lo) {
    uint32_t h;
    asm("cvt.rn.bf16x2.f32 %0, %1, %2;" : "=r"(h) : "f"(b), "f"(a));
    float fa = __uint_as_float(h << 16);
    float fb = __uint_as_float(h & 0xffff0000u);
    float ra = a - fa;
    float rb = b - fb;
    uint32_t l;
    asm("cvt.rn.bf16x2.f32 %0, %1, %2;" : "=r"(l) : "f"(rb), "f"(ra));
    hi = h; lo = l;
}
__device__ __forceinline__ uint32_t pack_f16(float a, float b) {
    __half2 h = __floats2half2_rn(a, b);
    return *(uint32_t*)&h;
}

// ---------------------------------------------------------------------------
// Conversion kernels
// ---------------------------------------------------------------------------
// x, wq, wo -> single fp16 planes
__global__ void conv3(const float4* __restrict__ s0, const float4* __restrict__ s1,
                      const float4* __restrict__ s2,
                      uint2* xf, uint2* wqf, uint2* wof)
{
    const int mode = blockIdx.y;
    const float4* src = (mode == 0) ? s0 : (mode == 1) ? s1 : s2;
    uint2* dst = (mode == 0) ? xf : (mode == 1) ? wqf : wof;
    const int n4 = PLANE_U32 / 2;
    for (int i = blockIdx.x * blockDim.x + threadIdx.x; i < n4;
         i += gridDim.x * blockDim.x) {
        float4 v = src[i];
        dst[i] = make_uint2(pack_f16(v.x, v.y), pack_f16(v.z, v.w));
    }
}

// K: (b,s,g,d) fp32 -> bf16 hi/lo planes (b,g,s,d).  V: -> fp16x2 plane.
__global__ void conv_kv4(const float4* __restrict__ ksrc, const float4* __restrict__ vsrc,
                         uint2* kh, uint2* kl, uint2* vf)
{
    const int isV = blockIdx.y;
    const float4* src = isV ? vsrc : ksrc;
    const int n4 = KV_U32 / 2;
    for (int p = blockIdx.x * blockDim.x + threadIdx.x; p < n4;
         p += gridDim.x * blockDim.x) {
        const int d4 = p & 31;
        const int s = (p >> 5) & 2047;
        const int g = (p >> 16) & 7;
        const int b = p >> 19;
        float4 v = src[(((size_t)b * SEQ + s) * NKVH + g) * 32 + d4];
        if (isV) {
            vf[p] = make_uint2(pack_f16(v.x, v.y), pack_f16(v.z, v.w));
        } else {
            uint32_t ha, la, hb, lb;
            pack_hilo(v.x, v.y, ha, la);
            pack_hilo(v.z, v.w, hb, lb);
            kh[p] = make_uint2(ha, hb);
            kl[p] = make_uint2(la, lb);
        }
    }
}

// ---------------------------------------------------------------------------
// Single-pass fp16 GEMM: C[M,N] = A[M,K] @ B[N,K]^T.
// CTA 128x128, 8 warps (32x64), K-chunk 32, 3 x 16KB stages (Af 8K | Bf 8K),
// 2 CTAs/SM.
// EPI=0: fp32 store to C.  EPI=1: Q-proj (freqs * QSC2 -> bf16 hi/lo Qh/Ql).
// ---------------------------------------------------------------------------
#define GEMM1_SMEM (3 * 16384)

template <int EPI>
__global__ __launch_bounds__(256, 2) void gemm_f16(
    const uint32_t* __restrict__ Af, const uint32_t* __restrict__ Bf,
    float* __restrict__ C, const float* __restrict__ freqs,
    uint32_t* __restrict__ Qh, uint32_t* __restrict__ Ql)
{
    extern __shared__ char sm[];
    const uint32_t smb = smem_to_u32(sm);
    const int tid = threadIdx.x;
    const int wid = tid >> 5;
    const int lane = tid & 31;
    const int wn = wid & 1;
    const int wm = wid >> 1;
    const int m0 = blockIdx.y * 128;
    const int n0 = blockIdx.x * 128;

    float acc[2][8][4];
#pragma unroll
    for (int i = 0; i < 2; i++)
#pragma unroll
        for (int j = 0; j < 8; j++)
#pragma unroll
            for (int v = 0; v < 4; v++) acc[i][j][v] = 0.0f;

    auto load_stage = [&](int ch, int st) {
        const uint32_t sbase = smb + (uint32_t)st * 16384u;
        const int kc2 = ch * 16;
#pragma unroll
        for (int t = tid; t < 1024; t += 256) {
            const int plane = t >> 9;            // Af Bf
            const int i = t & 511;
            const int row = i >> 2, ck = i & 3;
            const uint32_t dst = sbase + plane * 8192u + SWZ64(row * 64 + ck * 16);
            const uint32_t* bp = plane ? Bf : Af;
            const int r0 = plane ? n0 : m0;
            cp16(dst, bp + (size_t)(r0 + row) * 2048 + kc2 + ck * 4);
        }
    };

    const int q = lane >> 3;
    const int wi = lane & 7;
    const int arow_base = wm * 32 + wi + ((q & 1) ? 8 : 0);
    const int akb_off = (q & 2) ? 16 : 0;
    const int brow_base = wn * 64 + wi + ((q & 2) ? 8 : 0);
    const int bkb_off = (q & 1) ? 16 : 0;

    load_stage(0, 0); CP_COMMIT;
    load_stage(1, 1); CP_COMMIT;

    for (int ch = 0; ch < 128; ++ch) {
        if (ch < 127) CP_WAIT(1); else CP_WAIT(0);
        __syncthreads();
        if (ch + 2 < 128) { load_stage(ch + 2, (ch + 2) % 3); CP_COMMIT; }

        const uint32_t sbase = smb + (uint32_t)(ch % 3) * 16384u;
        const uint32_t pAf = sbase, pBf = sbase + 8192u;

#pragma unroll
        for (int ks = 0; ks < 2; ++ks) {
            const int kb0 = ks * 32;
            uint32_t af[2][4];
#pragma unroll
            for (int mt = 0; mt < 2; ++mt) {
                const int r = arow_base + mt * 16;
                const uint32_t off = SWZ64(r * 64 + kb0 + akb_off);
                ldsm_x4(af[mt][0], af[mt][1], af[mt][2], af[mt][3], pAf + off);
            }
#pragma unroll
            for (int np = 0; np < 4; ++np) {
                const int rn = brow_base + np * 16;
                const uint32_t offb = SWZ64(rn * 64 + kb0 + bkb_off);
                uint32_t bf[4];
                ldsm_x4(bf[0], bf[1], bf[2], bf[3], pBf + offb);
#pragma unroll
                for (int mt = 0; mt < 2; ++mt) {
                    mma_f16(acc[mt][np * 2],     af[mt], bf[0], bf[1]);
                    mma_f16(acc[mt][np * 2 + 1], af[mt], bf[2], bf[3]);
                }
            }
        }
    }

    const int rl = lane >> 2;
    const int cl = (lane & 3) * 2;
#pragma unroll
    for (int mt = 0; mt < 2; ++mt) {
#pragma unroll
        for (int nn = 0; nn < 8; ++nn) {
            const int r = m0 + wm * 32 + mt * 16 + rl;
            const int c = n0 + wn * 64 + nn * 8 + cl;
#pragma unroll
            for (int half = 0; half < 2; ++half) {
                const int rr = r + half * 8;
                const float v0 = acc[mt][nn][half * 2];
                const float v1 = acc[mt][nn][half * 2 + 1];
                if (EPI == 0) {
                    *(float2*)&C[(size_t)rr * DMODEL + c] = make_float2(v0, v1);
                } else {
                    const int b = rr >> 11;
                    const int s = rr & (SEQ - 1);
                    const int h = c >> 7;
                    const int d = c & (HEADD - 1);
                    float2 f = *(const float2*)&freqs[(size_t)s * 64 + (d & 63)];
                    uint32_t hi, lo;
                    pack_hilo(v0 * f.x * QSC2, v1 * f.y * QSC2, hi, lo);
                    const size_t idx = (((size_t)b * NHEADS + h) * SEQ + s) * 64 + (d >> 1);
                    Qh[idx] = hi; Ql[idx] = lo;
                }
            }
        }
    }
}

// ---------------------------------------------------------------------------
// Tensor-core flash attention (causal). S = bf16 hi/lo 3-pass (base-2 softmax);
// PV = single-pass fp16. Output -> single fp16 plane. (proven R13/R14 config)
// ---------------------------------------------------------------------------
#define ATT_QOFF 73728u
#define ATT_SMEM (73728 + 32768)

__global__ __launch_bounds__(128, 2) void attn_tc(
    const uint32_t* __restrict__ Qhi, const uint32_t* __restrict__ Qlo,
    const uint32_t* __restrict__ Khi, const uint32_t* __restrict__ Klo,
    const uint32_t* __restrict__ Vf,
    uint32_t* __restrict__ Of)
{
    extern __shared__ char sm[];
    const uint32_t smb = smem_to_u32(sm);
    const int tid = threadIdx.x;
    const int w = tid >> 5;
    const int lane = tid & 31;
    const int bx = gridDim.x - 1 - blockIdx.x;   // big tiles first
    const int by = blockIdx.y;
    const int b = by >> 5, h = by & 31, g = h >> 2;
    const int q0 = bx * 64;
    const int nb = 2 * bx + 2;                   // KV blocks of 32 rows

    const size_t qbase = (((size_t)b * NHEADS + h) * SEQ + q0) * 64;
#pragma unroll
    for (int t = tid; t < 2048; t += 128) {
        const int plane = t >> 10;
        const int i = t & 1023;
        const int row = i >> 4, ck = i & 15;
        const uint32_t dst = smb + ATT_QOFF + plane * 16384u + SWZ256(row * 256 + ck * 16);
        cp16(dst, (plane ? Qlo : Qhi) + qbase + (size_t)row * 64 + ck * 4);
    }
    CP_COMMIT;

    const size_t kvbase = ((size_t)b * NKVH + g) * KVLEN * 64;
    auto load_kv = [&](int jb, int region) {
        const uint32_t sb = smb + (uint32_t)region * 24576u;
        const int kv0 = jb * 32;
#pragma unroll
        for (int t = tid; t < 1536; t += 128) {
            const int plane = t >> 9;                 // Khi Klo Vf
            const int i = t & 511;
            const int row = i >> 4, ck = i & 15;
            const uint32_t dst = sb + plane * 8192u + SWZ256(row * 256 + ck * 16);
            const uint32_t* base = (plane == 0) ? Khi : (plane == 1) ? Klo : Vf;
            cp16(dst, base + kvbase + (size_t)(kv0 + row) * 64 + ck * 4);
        }
    };

    load_kv(0, 0); CP_COMMIT;
    load_kv(1, 1); CP_COMMIT;
    CP_WAIT(2);                 // Q done
    __syncthreads();

    const int wi = lane & 7, qq = lane >> 3;
    const int arow = w * 16 + wi + ((qq & 1) ? 8 : 0);
    const int akoff = (qq & 2) ? 16 : 0;
    uint32_t qh[8][4], ql[8][4];
#pragma unroll
    for (int ks = 0; ks < 8; ks++) {
        const uint32_t off = SWZ256(arow * 256 + ks * 32 + akoff);
        ldsm_x4(qh[ks][0], qh[ks][1], qh[ks][2], qh[ks][3], smb + ATT_QOFF + off);
        ldsm_x4(ql[ks][0], ql[ks][1], ql[ks][2], ql[ks][3], smb + ATT_QOFF + 16384u + off);
    }

    float oacc[16][4];
#pragma unroll
    for (int i = 0; i < 16; i++)
#pragma unroll
        for (int v = 0; v < 4; v++) oacc[i][v] = 0.0f;
    float mprev0 = -INFINITY, mprev1 = -INFINITY;
    float lsum0 = 0.0f, lsum1 = 0.0f;

    const int rl = lane >> 2, cl2 = (lane & 3) * 2;
    const int row0g = q0 + w * 16 + rl;
    const int row1g = row0g + 8;
    const int brow = wi + ((qq & 2) ? 8 : 0);
    const int bkoff = (qq & 1) ? 16 : 0;
    const int vkr = (lane & 7) + ((lane & 8) ? 8 : 0);
    const int vnoff = (lane & 16) ? 16 : 0;

    for (int jb = 0; jb < nb; ++jb) {
        if (jb < nb - 1) CP_WAIT(1); else CP_WAIT(0);
        __syncthreads();
        if (jb + 2 < nb) { load_kv(jb + 2, (jb + 2) % 3); CP_COMMIT; }
        const uint32_t sb = smb + (uint32_t)(jb % 3) * 24576u;

        float sacc[4][4];
#pragma unroll
        for (int i = 0; i < 4; i++)
#pragma unroll
            for (int v = 0; v < 4; v++) sacc[i][v] = 0.0f;
#pragma unroll
        for (int ks = 0; ks < 8; ks++) {
#pragma unroll
            for (int nt2 = 0; nt2 < 2; nt2++) {
                const uint32_t off = SWZ256((nt2 * 16 + brow) * 256 + ks * 32 + bkoff);
                uint32_t bh[4], bl[4];
                ldsm_x4(bh[0], bh[1], bh[2], bh[3], sb + off);
                ldsm_x4(bl[0], bl[1], bl[2], bl[3], sb + 8192u + off);
                mma_bf16(sacc[nt2 * 2],     qh[ks], bh[0], bh[1]);
                mma_bf16(sacc[nt2 * 2 + 1], qh[ks], bh[2], bh[3]);
                mma_bf16(sacc[nt2 * 2],     qh[ks], bl[0], bl[1]);
                mma_bf16(sacc[nt2 * 2 + 1], qh[ks], bl[2], bl[3]);
                mma_bf16(sacc[nt2 * 2],     ql[ks], bh[0], bh[1]);
                mma_bf16(sacc[nt2 * 2 + 1], ql[ks], bh[2], bh[3]);
            }
        }

        if (jb >= 2 * bx) {
            const int kv0 = jb * 32;
#pragma unroll
            for (int nt = 0; nt < 4; nt++) {
                const int c0 = kv0 + nt * 8 + cl2;
                const int c1 = c0 + 1;
                if (c0 > row0g) sacc[nt][0] = -1e30f;
                if (c1 > row0g) sacc[nt][1] = -1e30f;
                if (c0 > row1g) sacc[nt][2] = -1e30f;
                if (c1 > row1g) sacc[nt][3] = -1e30f;
            }
        }

        float mx0 = -1e30f, mx1 = -1e30f;
#pragma unroll
        for (int nt = 0; nt < 4; nt++) {
            mx0 = fmaxf(mx0, fmaxf(sacc[nt][0], sacc[nt][1]));
            mx1 = fmaxf(mx1, fmaxf(sacc[nt][2], sacc[nt][3]));
        }
        mx0 = fmaxf(mx0, __shfl_xor_sync(0xffffffffu, mx0, 1));
        mx0 = fmaxf(mx0, __shfl_xor_sync(0xffffffffu, mx0, 2));
        mx1 = fmaxf(mx1, __shfl_xor_sync(0xffffffffu, mx1, 1));
        mx1 = fmaxf(mx1, __shfl_xor_sync(0xffffffffu, mx1, 2));
        const float mnew0 = fmaxf(mprev0, mx0);
        const float mnew1 = fmaxf(mprev1, mx1);
        const float alpha0 = exp2f(mprev0 - mnew0);
        const float alpha1 = exp2f(mprev1 - mnew1);
        float rs0 = 0.0f, rs1 = 0.0f;
#pragma unroll
        for (int nt = 0; nt < 4; nt++) {
            sacc[nt][0] = exp2f(sacc[nt][0] - mnew0);
            sacc[nt][1] = exp2f(sacc[nt][1] - mnew0);
            sacc[nt][2] = exp2f(sacc[nt][2] - mnew1);
            sacc[nt][3] = exp2f(sacc[nt][3] - mnew1);
            rs0 += sacc[nt][0] + sacc[nt][1];
            rs1 += sacc[nt][2] + sacc[nt][3];
        }
        rs0 += __shfl_xor_sync(0xffffffffu, rs0, 1);
        rs0 += __shfl_xor_sync(0xffffffffu, rs0, 2);
        rs1 += __shfl_xor_sync(0xffffffffu, rs1, 1);
        rs1 += __shfl_xor_sync(0xffffffffu, rs1, 2);
        lsum0 = lsum0 * alpha0 + rs0;
        lsum1 = lsum1 * alpha1 + rs1;
#pragma unroll
        for (int nt = 0; nt < 16; nt++) {
            oacc[nt][0] *= alpha0; oacc[nt][1] *= alpha0;
            oacc[nt][2] *= alpha1; oacc[nt][3] *= alpha1;
        }
        mprev0 = mnew0; mprev1 = mnew1;

#pragma unroll
        for (int jp = 0; jp < 2; jp++) {
            uint32_t pf[4];
            pf[0] = pack_f16(sacc[2 * jp][0],     sacc[2 * jp][1]);
            pf[1] = pack_f16(sacc[2 * jp][2],     sacc[2 * jp][3]);
            pf[2] = pack_f16(sacc[2 * jp + 1][0], sacc[2 * jp + 1][1]);
            pf[3] = pack_f16(sacc[2 * jp + 1][2], sacc[2 * jp + 1][3]);
#pragma unroll
            for (int nt2 = 0; nt2 < 8; nt2++) {
                const uint32_t off = SWZ256((jp * 16 + vkr) * 256 + nt2 * 32 + vnoff);
                uint32_t vh[4];
                ldsm_x4_t(vh[0], vh[1], vh[2], vh[3], sb + 16384u + off);
                mma_f16(oacc[nt2 * 2],     pf, vh[0], vh[1]);
                mma_f16(oacc[nt2 * 2 + 1], pf, vh[2], vh[3]);
            }
        }
    }

    const float inv0 = 1.0f / lsum0;
    const float inv1 = 1.0f / lsum1;
    const size_t r0 = ((size_t)b * SEQ + row0g) * 2048 + h * 64;
    const size_t r1 = ((size_t)b * SEQ + row1g) * 2048 + h * 64;
#pragma unroll
    for (int nt = 0; nt < 16; nt++) {
        const int d2 = (nt * 8 + cl2) >> 1;
        Of[r0 + d2] = pack_f16(oacc[nt][0] * inv0, oacc[nt][1] * inv0);
        Of[r1 + d2] = pack_f16(oacc[nt][2] * inv1, oacc[nt][3] * inv1);
    }
}

// ---------------------------------------------------------------------------
extern "C" void kernel_launch(void* const* d_in, const int* in_sizes, int n_in,
                              void* d_out, int out_size)
{
    (void)in_sizes; (void)n_in; (void)out_size;
    const float* x     = (const float*)d_in[0];
    const float* freqs = (const float*)d_in[1];
    const float* wq    = (const float*)d_in[3];
    const float* wo    = (const float*)d_in[6];
    const float* ck    = (const float*)d_in[7];
    const float* cv    = (const float*)d_in[8];
    float* out = (float*)d_out;

    void *xf, *wqf, *wof, *qhi, *qlo, *af, *khi, *klo, *vf;
    cudaGetSymbolAddress(&xf, g_xf);
    cudaGetSymbolAddress(&wqf, g_wqf);
    cudaGetSymbolAddress(&wof, g_wof);
    cudaGetSymbolAddress(&qhi, g_qhi);   cudaGetSymbolAddress(&qlo, g_qlo);
    cudaGetSymbolAddress(&af, g_af);
    cudaGetSymbolAddress(&khi, g_khi);   cudaGetSymbolAddress(&klo, g_klo);
    cudaGetSymbolAddress(&vf, g_vf);

    cudaFuncSetAttribute(gemm_f16<0>, cudaFuncAttributeMaxDynamicSharedMemorySize, GEMM1_SMEM);
    cudaFuncSetAttribute(gemm_f16<1>, cudaFuncAttributeMaxDynamicSharedMemorySize, GEMM1_SMEM);
    cudaFuncSetAttribute(attn_tc, cudaFuncAttributeMaxDynamicSharedMemorySize, ATT_SMEM);

    dim3 blk(256);
    conv3<<<dim3(2048, 3), blk>>>(
        (const float4*)x, (const float4*)wq, (const float4*)wo,
        (uint2*)xf, (uint2*)wqf, (uint2*)wof);
    conv_kv4<<<dim3(1024, 2), blk>>>(
        (const float4*)ck, (const float4*)cv,
        (uint2*)khi, (uint2*)klo, (uint2*)vf);

    gemm_f16<1><<<dim3(32, 32), blk, GEMM1_SMEM>>>(
        (const uint32_t*)xf, (const uint32_t*)wqf,
        nullptr, freqs, (uint32_t*)qhi, (uint32_t*)qlo);

    attn_tc<<<dim3(32, 64), dim3(128), ATT_SMEM>>>(
        (const uint32_t*)qhi, (const uint32_t*)qlo,
        (const uint32_t*)khi, (const uint32_t*)klo,
        (const uint32_t*)vf,
        (uint32_t*)af);

    gemm_f16<0><<<dim3(32, 32), blk, GEMM1_SMEM>>>(
        (const uint32_t*)af, (const uint32_t*)wof,
        out, nullptr, nullptr, nullptr);
}

// round 16
// speedup vs baseline: 2.2474x; 1.0597x over previous
#include <cuda_runtime.h>
#include <cuda_bf16.h>
#include <cuda_fp16.h>
#include <math.h>
#include <stdint.h>

#define BATCH 2
#define SEQ   2048
#define DMODEL 4096
#define NHEADS 32
#define NKVH  8
#define HEADD 128
#define KVLEN 2048

// QSCALE * log2(e): softmax done in base-2
#define QSC2 (0.08838834764831845f * 1.4426950408889634f)

// ---------------------------------------------------------------------------
// Global scratch.
// x/wq/wo/q: single fp16 planes. K: fp16 hi/lo. V: fp16. attn out: fp16.
// ---------------------------------------------------------------------------
#define PLANE_U32 (8388608)
__device__ uint32_t g_xf[PLANE_U32];                       // x (b*s, k) fp16
__device__ uint32_t g_wqf[PLANE_U32];                      // wq (n, k) fp16
__device__ uint32_t g_wof[PLANE_U32];                      // wo (n, k) fp16
__device__ uint32_t g_qf[PLANE_U32];                       // q (b,h,s,d) fp16
__device__ uint32_t g_af[PLANE_U32];                       // attn out (b*s, h*d) fp16
#define KV_U32 (2097152)
__device__ uint32_t g_khi[KV_U32], g_klo[KV_U32];          // (b,g,s,d) fp16 hi/lo
__device__ uint32_t g_vf[KV_U32];                          // (b,g,s,d) fp16x2

// ---------------------------------------------------------------------------
__device__ __forceinline__ uint32_t smem_to_u32(const void* p) {
    uint32_t a;
    asm("{ .reg .u64 t; cvta.to.shared.u64 t, %1; cvt.u32.u64 %0, t; }" : "=r"(a) : "l"(p));
    return a;
}
#define SWZ64(off)  ((uint32_t)(off) ^ ((((uint32_t)(off)) >> 3) & 0x30u))
#define SWZ256(off) ((uint32_t)(off) ^ ((((uint32_t)(off)) >> 4) & 0x70u))

__device__ __forceinline__ void cp16(uint32_t dst, const void* src) {
    asm volatile("cp.async.cg.shared.global [%0], [%1], 16;" :: "r"(dst), "l"(src));
}
#define CP_COMMIT asm volatile("cp.async.commit_group;" ::: "memory")
#define CP_WAIT(n) asm volatile("cp.async.wait_group %0;" :: "n"(n) : "memory")

__device__ __forceinline__ void ldsm_x4(uint32_t& r0, uint32_t& r1, uint32_t& r2, uint32_t& r3,
                                        uint32_t addr) {
    asm volatile("ldmatrix.sync.aligned.m8n8.x4.shared.b16 {%0,%1,%2,%3}, [%4];"
                 : "=r"(r0), "=r"(r1), "=r"(r2), "=r"(r3) : "r"(addr));
}
__device__ __forceinline__ void ldsm_x4_t(uint32_t& r0, uint32_t& r1, uint32_t& r2, uint32_t& r3,
                                          uint32_t addr) {
    asm volatile("ldmatrix.sync.aligned.m8n8.x4.trans.shared.b16 {%0,%1,%2,%3}, [%4];"
                 : "=r"(r0), "=r"(r1), "=r"(r2), "=r"(r3) : "r"(addr));
}
__device__ __forceinline__ void mma_f16(float* d, const uint32_t* a, uint32_t b0, uint32_t b1) {
    asm volatile(
        "mma.sync.aligned.m16n8k16.row.col.f32.f16.f16.f32 "
        "{%0,%1,%2,%3}, {%4,%5,%6,%7}, {%8,%9}, {%0,%1,%2,%3};"
        : "+f"(d[0]), "+f"(d[1]), "+f"(d[2]), "+f"(d[3])
        : "r"(a[0]), "r"(a[1]), "r"(a[2]), "r"(a[3]), "r"(b0), "r"(b1));
}
__device__ __forceinline__ uint32_t pack_f16(float a, float b) {
    __half2 h = __floats2half2_rn(a, b);
    return *(uint32_t*)&h;
}
__device__ __forceinline__ void pack_f16_hilo(float a, float b, uint32_t& hi, uint32_t& lo) {
    __half2 h = __floats2half2_rn(a, b);
    float2 hf = __half22float2(h);
    __half2 l = __floats2half2_rn(a - hf.x, b - hf.y);
    hi = *(uint32_t*)&h;
    lo = *(uint32_t*)&l;
}

// ---------------------------------------------------------------------------
// Conversion kernels
// ---------------------------------------------------------------------------
// x, wq, wo -> single fp16 planes
__global__ void conv3(const float4* __restrict__ s0, const float4* __restrict__ s1,
                      const float4* __restrict__ s2,
                      uint2* xf, uint2* wqf, uint2* wof)
{
    const int mode = blockIdx.y;
    const float4* src = (mode == 0) ? s0 : (mode == 1) ? s1 : s2;
    uint2* dst = (mode == 0) ? xf : (mode == 1) ? wqf : wof;
    const int n4 = PLANE_U32 / 2;
    for (int i = blockIdx.x * blockDim.x + threadIdx.x; i < n4;
         i += gridDim.x * blockDim.x) {
        float4 v = src[i];
        dst[i] = make_uint2(pack_f16(v.x, v.y), pack_f16(v.z, v.w));
    }
}

// K: (b,s,g,d) fp32 -> fp16 hi/lo planes (b,g,s,d).  V: -> fp16x2 plane.
__global__ void conv_kv4(const float4* __restrict__ ksrc, const float4* __restrict__ vsrc,
                         uint2* kh, uint2* kl, uint2* vf)
{
    const int isV = blockIdx.y;
    const float4* src = isV ? vsrc : ksrc;
    const int n4 = KV_U32 / 2;
    for (int p = blockIdx.x * blockDim.x + threadIdx.x; p < n4;
         p += gridDim.x * blockDim.x) {
        const int d4 = p & 31;
        const int s = (p >> 5) & 2047;
        const int g = (p >> 16) & 7;
        const int b = p >> 19;
        float4 v = src[(((size_t)b * SEQ + s) * NKVH + g) * 32 + d4];
        if (isV) {
            vf[p] = make_uint2(pack_f16(v.x, v.y), pack_f16(v.z, v.w));
        } else {
            uint32_t ha, la, hb, lb;
            pack_f16_hilo(v.x, v.y, ha, la);
            pack_f16_hilo(v.z, v.w, hb, lb);
            kh[p] = make_uint2(ha, hb);
            kl[p] = make_uint2(la, lb);
        }
    }
}

// ---------------------------------------------------------------------------
// Single-pass fp16 GEMM: C[M,N] = A[M,K] @ B[N,K]^T. (proven R15 config)
// CTA 128x128, 8 warps (32x64), K-chunk 32, 3 x 16KB stages, 2 CTAs/SM.
// EPI=0: fp32 store to C.  EPI=1: Q-proj (freqs * QSC2 -> fp16 plane Qf).
// ---------------------------------------------------------------------------
#define GEMM1_SMEM (3 * 16384)

template <int EPI>
__global__ __launch_bounds__(256, 2) void gemm_f16(
    const uint32_t* __restrict__ Af, const uint32_t* __restrict__ Bf,
    float* __restrict__ C, const float* __restrict__ freqs,
    uint32_t* __restrict__ Qf)
{
    extern __shared__ char sm[];
    const uint32_t smb = smem_to_u32(sm);
    const int tid = threadIdx.x;
    const int wid = tid >> 5;
    const int lane = tid & 31;
    const int wn = wid & 1;
    const int wm = wid >> 1;
    const int m0 = blockIdx.y * 128;
    const int n0 = blockIdx.x * 128;

    float acc[2][8][4];
#pragma unroll
    for (int i = 0; i < 2; i++)
#pragma unroll
        for (int j = 0; j < 8; j++)
#pragma unroll
            for (int v = 0; v < 4; v++) acc[i][j][v] = 0.0f;

    auto load_stage = [&](int ch, int st) {
        const uint32_t sbase = smb + (uint32_t)st * 16384u;
        const int kc2 = ch * 16;
#pragma unroll
        for (int t = tid; t < 1024; t += 256) {
            const int plane = t >> 9;            // Af Bf
            const int i = t & 511;
            const int row = i >> 2, ck = i & 3;
            const uint32_t dst = sbase + plane * 8192u + SWZ64(row * 64 + ck * 16);
            const uint32_t* bp = plane ? Bf : Af;
            const int r0 = plane ? n0 : m0;
            cp16(dst, bp + (size_t)(r0 + row) * 2048 + kc2 + ck * 4);
        }
    };

    const int q = lane >> 3;
    const int wi = lane & 7;
    const int arow_base = wm * 32 + wi + ((q & 1) ? 8 : 0);
    const int akb_off = (q & 2) ? 16 : 0;
    const int brow_base = wn * 64 + wi + ((q & 2) ? 8 : 0);
    const int bkb_off = (q & 1) ? 16 : 0;

    load_stage(0, 0); CP_COMMIT;
    load_stage(1, 1); CP_COMMIT;

    for (int ch = 0; ch < 128; ++ch) {
        if (ch < 127) CP_WAIT(1); else CP_WAIT(0);
        __syncthreads();
        if (ch + 2 < 128) { load_stage(ch + 2, (ch + 2) % 3); CP_COMMIT; }

        const uint32_t sbase = smb + (uint32_t)(ch % 3) * 16384u;
        const uint32_t pAf = sbase, pBf = sbase + 8192u;

#pragma unroll
        for (int ks = 0; ks < 2; ++ks) {
            const int kb0 = ks * 32;
            uint32_t af[2][4];
#pragma unroll
            for (int mt = 0; mt < 2; ++mt) {
                const int r = arow_base + mt * 16;
                const uint32_t off = SWZ64(r * 64 + kb0 + akb_off);
                ldsm_x4(af[mt][0], af[mt][1], af[mt][2], af[mt][3], pAf + off);
            }
#pragma unroll
            for (int np = 0; np < 4; ++np) {
                const int rn = brow_base + np * 16;
                const uint32_t offb = SWZ64(rn * 64 + kb0 + bkb_off);
                uint32_t bf[4];
                ldsm_x4(bf[0], bf[1], bf[2], bf[3], pBf + offb);
#pragma unroll
                for (int mt = 0; mt < 2; ++mt) {
                    mma_f16(acc[mt][np * 2],     af[mt], bf[0], bf[1]);
                    mma_f16(acc[mt][np * 2 + 1], af[mt], bf[2], bf[3]);
                }
            }
        }
    }

    const int rl = lane >> 2;
    const int cl = (lane & 3) * 2;
#pragma unroll
    for (int mt = 0; mt < 2; ++mt) {
#pragma unroll
        for (int nn = 0; nn < 8; ++nn) {
            const int r = m0 + wm * 32 + mt * 16 + rl;
            const int c = n0 + wn * 64 + nn * 8 + cl;
#pragma unroll
            for (int half = 0; half < 2; ++half) {
                const int rr = r + half * 8;
                const float v0 = acc[mt][nn][half * 2];
                const float v1 = acc[mt][nn][half * 2 + 1];
                if (EPI == 0) {
                    *(float2*)&C[(size_t)rr * DMODEL + c] = make_float2(v0, v1);
                } else {
                    const int b = rr >> 11;
                    const int s = rr & (SEQ - 1);
                    const int h = c >> 7;
                    const int d = c & (HEADD - 1);
                    float2 f = *(const float2*)&freqs[(size_t)s * 64 + (d & 63)];
                    const size_t idx = (((size_t)b * NHEADS + h) * SEQ + s) * 64 + (d >> 1);
                    Qf[idx] = pack_f16(v0 * f.x * QSC2, v1 * f.y * QSC2);
                }
            }
        }
    }
}

// ---------------------------------------------------------------------------
// Tensor-core flash attention (causal).
// S = 2-pass fp16 (Qf fp16; K fp16 hi/lo), base-2 softmax; PV = fp16 1-pass.
// CTA: 64 q-rows, 4 warps, KV blocks of 32. Stages 3x24KB + Q 16KB. 2 CTAs/SM.
// ---------------------------------------------------------------------------
#define ATT_QOFF 73728u
#define ATT_SMEM (73728 + 16384)

__global__ __launch_bounds__(128, 2) void attn_tc(
    const uint32_t* __restrict__ Qf,
    const uint32_t* __restrict__ Khi, const uint32_t* __restrict__ Klo,
    const uint32_t* __restrict__ Vf,
    uint32_t* __restrict__ Of)
{
    extern __shared__ char sm[];
    const uint32_t smb = smem_to_u32(sm);
    const int tid = threadIdx.x;
    const int w = tid >> 5;
    const int lane = tid & 31;
    const int bx = gridDim.x - 1 - blockIdx.x;   // big tiles first
    const int by = blockIdx.y;
    const int b = by >> 5, h = by & 31, g = h >> 2;
    const int q0 = bx * 64;
    const int nb = 2 * bx + 2;                   // KV blocks of 32 rows

    // --- Q load (64 rows x 1 plane = 16KB) ---
    const size_t qbase = (((size_t)b * NHEADS + h) * SEQ + q0) * 64;
#pragma unroll
    for (int t = tid; t < 1024; t += 128) {
        const int row = t >> 4, ck = t & 15;
        const uint32_t dst = smb + ATT_QOFF + SWZ256(row * 256 + ck * 16);
        cp16(dst, Qf + qbase + (size_t)row * 64 + ck * 4);
    }
    CP_COMMIT;

    const size_t kvbase = ((size_t)b * NKVH + g) * KVLEN * 64;
    auto load_kv = [&](int jb, int region) {
        const uint32_t sb = smb + (uint32_t)region * 24576u;
        const int kv0 = jb * 32;
#pragma unroll
        for (int t = tid; t < 1536; t += 128) {
            const int plane = t >> 9;                 // Khi Klo Vf
            const int i = t & 511;
            const int row = i >> 4, ck = i & 15;
            const uint32_t dst = sb + plane * 8192u + SWZ256(row * 256 + ck * 16);
            const uint32_t* base = (plane == 0) ? Khi : (plane == 1) ? Klo : Vf;
            cp16(dst, base + kvbase + (size_t)(kv0 + row) * 64 + ck * 4);
        }
    };

    load_kv(0, 0); CP_COMMIT;
    load_kv(1, 1); CP_COMMIT;
    CP_WAIT(2);                 // Q done
    __syncthreads();

    // --- preload Q fragments ---
    const int wi = lane & 7, qq = lane >> 3;
    const int arow = w * 16 + wi + ((qq & 1) ? 8 : 0);
    const int akoff = (qq & 2) ? 16 : 0;
    uint32_t qf[8][4];
#pragma unroll
    for (int ks = 0; ks < 8; ks++) {
        const uint32_t off = SWZ256(arow * 256 + ks * 32 + akoff);
        ldsm_x4(qf[ks][0], qf[ks][1], qf[ks][2], qf[ks][3], smb + ATT_QOFF + off);
    }

    float oacc[16][4];
#pragma unroll
    for (int i = 0; i < 16; i++)
#pragma unroll
        for (int v = 0; v < 4; v++) oacc[i][v] = 0.0f;
    float mprev0 = -INFINITY, mprev1 = -INFINITY;
    float lsum0 = 0.0f, lsum1 = 0.0f;

    const int rl = lane >> 2, cl2 = (lane & 3) * 2;
    const int row0g = q0 + w * 16 + rl;
    const int row1g = row0g + 8;
    const int brow = wi + ((qq & 2) ? 8 : 0);
    const int bkoff = (qq & 1) ? 16 : 0;
    const int vkr = (lane & 7) + ((lane & 8) ? 8 : 0);
    const int vnoff = (lane & 16) ? 16 : 0;

    for (int jb = 0; jb < nb; ++jb) {
        if (jb < nb - 1) CP_WAIT(1); else CP_WAIT(0);
        __syncthreads();
        if (jb + 2 < nb) { load_kv(jb + 2, (jb + 2) % 3); CP_COMMIT; }
        const uint32_t sb = smb + (uint32_t)(jb % 3) * 24576u;

        // --- S = Qf @ (Khi + Klo)^T (2-pass fp16), log2 domain ---
        float sacc[4][4];
#pragma unroll
        for (int i = 0; i < 4; i++)
#pragma unroll
            for (int v = 0; v < 4; v++) sacc[i][v] = 0.0f;
#pragma unroll
        for (int ks = 0; ks < 8; ks++) {
#pragma unroll
            for (int nt2 = 0; nt2 < 2; nt2++) {
                const uint32_t off = SWZ256((nt2 * 16 + brow) * 256 + ks * 32 + bkoff);
                uint32_t bh[4], bl[4];
                ldsm_x4(bh[0], bh[1], bh[2], bh[3], sb + off);
                ldsm_x4(bl[0], bl[1], bl[2], bl[3], sb + 8192u + off);
                mma_f16(sacc[nt2 * 2],     qf[ks], bh[0], bh[1]);
                mma_f16(sacc[nt2 * 2 + 1], qf[ks], bh[2], bh[3]);
                mma_f16(sacc[nt2 * 2],     qf[ks], bl[0], bl[1]);
                mma_f16(sacc[nt2 * 2 + 1], qf[ks], bl[2], bl[3]);
            }
        }

        // --- causal mask ---
        if (jb >= 2 * bx) {
            const int kv0 = jb * 32;
#pragma unroll
            for (int nt = 0; nt < 4; nt++) {
                const int c0 = kv0 + nt * 8 + cl2;
                const int c1 = c0 + 1;
                if (c0 > row0g) sacc[nt][0] = -1e30f;
                if (c1 > row0g) sacc[nt][1] = -1e30f;
                if (c0 > row1g) sacc[nt][2] = -1e30f;
                if (c1 > row1g) sacc[nt][3] = -1e30f;
            }
        }

        // --- online softmax (base 2) ---
        float mx0 = -1e30f, mx1 = -1e30f;
#pragma unroll
        for (int nt = 0; nt < 4; nt++) {
            mx0 = fmaxf(mx0, fmaxf(sacc[nt][0], sacc[nt][1]));
            mx1 = fmaxf(mx1, fmaxf(sacc[nt][2], sacc[nt][3]));
        }
        mx0 = fmaxf(mx0, __shfl_xor_sync(0xffffffffu, mx0, 1));
        mx0 = fmaxf(mx0, __shfl_xor_sync(0xffffffffu, mx0, 2));
        mx1 = fmaxf(mx1, __shfl_xor_sync(0xffffffffu, mx1, 1));
        mx1 = fmaxf(mx1, __shfl_xor_sync(0xffffffffu, mx1, 2));
        const float mnew0 = fmaxf(mprev0, mx0);
        const float mnew1 = fmaxf(mprev1, mx1);
        const float alpha0 = exp2f(mprev0 - mnew0);
        const float alpha1 = exp2f(mprev1 - mnew1);
        float rs0 = 0.0f, rs1 = 0.0f;
#pragma unroll
        for (int nt = 0; nt < 4; nt++) {
            sacc[nt][0] = exp2f(sacc[nt][0] - mnew0);
            sacc[nt][1] = exp2f(sacc[nt][1] - mnew0);
            sacc[nt][2] = exp2f(sacc[nt][2] - mnew1);
            sacc[nt][3] = exp2f(sacc[nt][3] - mnew1);
            rs0 += sacc[nt][0] + sacc[nt][1];
            rs1 += sacc[nt][2] + sacc[nt][3];
        }
        rs0 += __shfl_xor_sync(0xffffffffu, rs0, 1);
        rs0 += __shfl_xor_sync(0xffffffffu, rs0, 2);
        rs1 += __shfl_xor_sync(0xffffffffu, rs1, 1);
        rs1 += __shfl_xor_sync(0xffffffffu, rs1, 2);
        lsum0 = lsum0 * alpha0 + rs0;
        lsum1 = lsum1 * alpha1 + rs1;
#pragma unroll
        for (int nt = 0; nt < 16; nt++) {
            oacc[nt][0] *= alpha0; oacc[nt][1] *= alpha0;
            oacc[nt][2] *= alpha1; oacc[nt][3] *= alpha1;
        }
        mprev0 = mnew0; mprev1 = mnew1;

        // --- O += P @ V (single-pass fp16) ---
#pragma unroll
        for (int jp = 0; jp < 2; jp++) {
            uint32_t pf[4];
            pf[0] = pack_f16(sacc[2 * jp][0],     sacc[2 * jp][1]);
            pf[1] = pack_f16(sacc[2 * jp][2],     sacc[2 * jp][3]);
            pf[2] = pack_f16(sacc[2 * jp + 1][0], sacc[2 * jp + 1][1]);
            pf[3] = pack_f16(sacc[2 * jp + 1][2], sacc[2 * jp + 1][3]);
#pragma unroll
            for (int nt2 = 0; nt2 < 8; nt2++) {
                const uint32_t off = SWZ256((jp * 16 + vkr) * 256 + nt2 * 32 + vnoff);
                uint32_t vh[4];
                ldsm_x4_t(vh[0], vh[1], vh[2], vh[3], sb + 16384u + off);
                mma_f16(oacc[nt2 * 2],     pf, vh[0], vh[1]);
                mma_f16(oacc[nt2 * 2 + 1], pf, vh[2], vh[3]);
            }
        }
    }

    // --- epilogue: normalize, fp16 pack, single plane (b*s, h*d) ---
    const float inv0 = 1.0f / lsum0;
    const float inv1 = 1.0f / lsum1;
    const size_t r0 = ((size_t)b * SEQ + row0g) * 2048 + h * 64;
    const size_t r1 = ((size_t)b * SEQ + row1g) * 2048 + h * 64;
#pragma unroll
    for (int nt = 0; nt < 16; nt++) {
        const int d2 = (nt * 8 + cl2) >> 1;
        Of[r0 + d2] = pack_f16(oacc[nt][0] * inv0, oacc[nt][1] * inv0);
        Of[r1 + d2] = pack_f16(oacc[nt][2] * inv1, oacc[nt][3] * inv1);
    }
}

// ---------------------------------------------------------------------------
extern "C" void kernel_launch(void* const* d_in, const int* in_sizes, int n_in,
                              void* d_out, int out_size)
{
    (void)in_sizes; (void)n_in; (void)out_size;
    const float* x     = (const float*)d_in[0];
    const float* freqs = (const float*)d_in[1];
    const float* wq    = (const float*)d_in[3];
    const float* wo    = (const float*)d_in[6];
    const float* ck    = (const float*)d_in[7];
    const float* cv    = (const float*)d_in[8];
    float* out = (float*)d_out;

    void *xf, *wqf, *wof, *qf, *af, *khi, *klo, *vf;
    cudaGetSymbolAddress(&xf, g_xf);
    cudaGetSymbolAddress(&wqf, g_wqf);
    cudaGetSymbolAddress(&wof, g_wof);
    cudaGetSymbolAddress(&qf, g_qf);
    cudaGetSymbolAddress(&af, g_af);
    cudaGetSymbolAddress(&khi, g_khi);   cudaGetSymbolAddress(&klo, g_klo);
    cudaGetSymbolAddress(&vf, g_vf);

    cudaFuncSetAttribute(gemm_f16<0>, cudaFuncAttributeMaxDynamicSharedMemorySize, GEMM1_SMEM);
    cudaFuncSetAttribute(gemm_f16<1>, cudaFuncAttributeMaxDynamicSharedMemorySize, GEMM1_SMEM);
    cudaFuncSetAttribute(attn_tc, cudaFuncAttributeMaxDynamicSharedMemorySize, ATT_SMEM);

    dim3 blk(256);
    conv3<<<dim3(2048, 3), blk>>>(
        (const float4*)x, (const float4*)wq, (const float4*)wo,
        (uint2*)xf, (uint2*)wqf, (uint2*)wof);
    conv_kv4<<<dim3(1024, 2), blk>>>(
        (const float4*)ck, (const float4*)cv,
        (uint2*)khi, (uint2*)klo, (uint2*)vf);

    gemm_f16<1><<<dim3(32, 32), blk, GEMM1_SMEM>>>(
        (const uint32_t*)xf, (const uint32_t*)wqf,
        nullptr, freqs, (uint32_t*)qf);

    attn_tc<<<dim3(32, 64), dim3(128), ATT_SMEM>>>(
        (const uint32_t*)qf,
        (const uint32_t*)khi, (const uint32_t*)klo,
        (const uint32_t*)vf,
        (uint32_t*)af);

    gemm_f16<0><<<dim3(32, 32), blk, GEMM1_SMEM>>>(
        (const uint32_t*)af, (const uint32_t*)wof,
        out, nullptr, nullptr);
}

// round 17
// speedup vs baseline: 2.4203x; 1.0769x over previous
#include <cuda_runtime.h>
#include <cuda_bf16.h>
#include <cuda_fp16.h>
#include <math.h>
#include <stdint.h>

#define BATCH 2
#define SEQ   2048
#define DMODEL 4096
#define NHEADS 32
#define NKVH  8
#define HEADD 128
#define KVLEN 2048

// QSCALE * log2(e): softmax done in base-2
#define QSC2 (0.08838834764831845f * 1.4426950408889634f)

// ---------------------------------------------------------------------------
// Global scratch: all operand planes single fp16 (packed fp16x2 in uint32).
// ---------------------------------------------------------------------------
#define PLANE_U32 (8388608)
__device__ uint32_t g_xf[PLANE_U32];                       // x (b*s, k) fp16
__device__ uint32_t g_wqf[PLANE_U32];                      // wq (n, k) fp16
__device__ uint32_t g_wof[PLANE_U32];                      // wo (n, k) fp16
__device__ uint32_t g_qf[PLANE_U32];                       // q (b,h,s,d) fp16
__device__ uint32_t g_af[PLANE_U32];                       // attn out (b*s, h*d) fp16
#define KV_U32 (2097152)
__device__ uint32_t g_kf[KV_U32];                          // (b,g,s,d) fp16x2
__device__ uint32_t g_vf[KV_U32];                          // (b,g,s,d) fp16x2

// ---------------------------------------------------------------------------
__device__ __forceinline__ uint32_t smem_to_u32(const void* p) {
    uint32_t a;
    asm("{ .reg .u64 t; cvta.to.shared.u64 t, %1; cvt.u32.u64 %0, t; }" : "=r"(a) : "l"(p));
    return a;
}
#define SWZ64(off)  ((uint32_t)(off) ^ ((((uint32_t)(off)) >> 3) & 0x30u))
#define SWZ256(off) ((uint32_t)(off) ^ ((((uint32_t)(off)) >> 4) & 0x70u))

__device__ __forceinline__ void cp16(uint32_t dst, const void* src) {
    asm volatile("cp.async.cg.shared.global [%0], [%1], 16;" :: "r"(dst), "l"(src));
}
#define CP_COMMIT asm volatile("cp.async.commit_group;" ::: "memory")
#define CP_WAIT(n) asm volatile("cp.async.wait_group %0;" :: "n"(n) : "memory")

__device__ __forceinline__ void ldsm_x4(uint32_t& r0, uint32_t& r1, uint32_t& r2, uint32_t& r3,
                                        uint32_t addr) {
    asm volatile("ldmatrix.sync.aligned.m8n8.x4.shared.b16 {%0,%1,%2,%3}, [%4];"
                 : "=r"(r0), "=r"(r1), "=r"(r2), "=r"(r3) : "r"(addr));
}
__device__ __forceinline__ void ldsm_x4_t(uint32_t& r0, uint32_t& r1, uint32_t& r2, uint32_t& r3,
                                          uint32_t addr) {
    asm volatile("ldmatrix.sync.aligned.m8n8.x4.trans.shared.b16 {%0,%1,%2,%3}, [%4];"
                 : "=r"(r0), "=r"(r1), "=r"(r2), "=r"(r3) : "r"(addr));
}
__device__ __forceinline__ void mma_f16(float* d, const uint32_t* a, uint32_t b0, uint32_t b1) {
    asm volatile(
        "mma.sync.aligned.m16n8k16.row.col.f32.f16.f16.f32 "
        "{%0,%1,%2,%3}, {%4,%5,%6,%7}, {%8,%9}, {%0,%1,%2,%3};"
        : "+f"(d[0]), "+f"(d[1]), "+f"(d[2]), "+f"(d[3])
        : "r"(a[0]), "r"(a[1]), "r"(a[2]), "r"(a[3]), "r"(b0), "r"(b1));
}
__device__ __forceinline__ uint32_t pack_f16(float a, float b) {
    __half2 h = __floats2half2_rn(a, b);
    return *(uint32_t*)&h;
}

// ---------------------------------------------------------------------------
// Conversion kernels
// ---------------------------------------------------------------------------
// x, wq, wo -> single fp16 planes
__global__ void conv3(const float4* __restrict__ s0, const float4* __restrict__ s1,
                      const float4* __restrict__ s2,
                      uint2* xf, uint2* wqf, uint2* wof)
{
    const int mode = blockIdx.y;
    const float4* src = (mode == 0) ? s0 : (mode == 1) ? s1 : s2;
    uint2* dst = (mode == 0) ? xf : (mode == 1) ? wqf : wof;
    const int n4 = PLANE_U32 / 2;
    for (int i = blockIdx.x * blockDim.x + threadIdx.x; i < n4;
         i += gridDim.x * blockDim.x) {
        float4 v = src[i];
        dst[i] = make_uint2(pack_f16(v.x, v.y), pack_f16(v.z, v.w));
    }
}

// K and V: (b,s,g,d) fp32 -> single fp16 planes (b,g,s,d).
__global__ void conv_kv4(const float4* __restrict__ ksrc, const float4* __restrict__ vsrc,
                         uint2* kf, uint2* vf)
{
    const int isV = blockIdx.y;
    const float4* src = isV ? vsrc : ksrc;
    uint2* dst = isV ? vf : kf;
    const int n4 = KV_U32 / 2;
    for (int p = blockIdx.x * blockDim.x + threadIdx.x; p < n4;
         p += gridDim.x * blockDim.x) {
        const int d4 = p & 31;
        const int s = (p >> 5) & 2047;
        const int g = (p >> 16) & 7;
        const int b = p >> 19;
        float4 v = src[(((size_t)b * SEQ + s) * NKVH + g) * 32 + d4];
        dst[p] = make_uint2(pack_f16(v.x, v.y), pack_f16(v.z, v.w));
    }
}

// ---------------------------------------------------------------------------
// Single-pass fp16 GEMM: C[M,N] = A[M,K] @ B[N,K]^T. (proven R15/R16 config)
// CTA 128x128, 8 warps (32x64), K-chunk 32, 3 x 16KB stages, 2 CTAs/SM.
// EPI=0: fp32 store to C.  EPI=1: Q-proj (freqs * QSC2 -> fp16 plane Qf).
// ---------------------------------------------------------------------------
#define GEMM1_SMEM (3 * 16384)

template <int EPI>
__global__ __launch_bounds__(256, 2) void gemm_f16(
    const uint32_t* __restrict__ Af, const uint32_t* __restrict__ Bf,
    float* __restrict__ C, const float* __restrict__ freqs,
    uint32_t* __restrict__ Qf)
{
    extern __shared__ char sm[];
    const uint32_t smb = smem_to_u32(sm);
    const int tid = threadIdx.x;
    const int wid = tid >> 5;
    const int lane = tid & 31;
    const int wn = wid & 1;
    const int wm = wid >> 1;
    const int m0 = blockIdx.y * 128;
    const int n0 = blockIdx.x * 128;

    float acc[2][8][4];
#pragma unroll
    for (int i = 0; i < 2; i++)
#pragma unroll
        for (int j = 0; j < 8; j++)
#pragma unroll
            for (int v = 0; v < 4; v++) acc[i][j][v] = 0.0f;

    auto load_stage = [&](int ch, int st) {
        const uint32_t sbase = smb + (uint32_t)st * 16384u;
        const int kc2 = ch * 16;
#pragma unroll
        for (int t = tid; t < 1024; t += 256) {
            const int plane = t >> 9;            // Af Bf
            const int i = t & 511;
            const int row = i >> 2, ck = i & 3;
            const uint32_t dst = sbase + plane * 8192u + SWZ64(row * 64 + ck * 16);
            const uint32_t* bp = plane ? Bf : Af;
            const int r0 = plane ? n0 : m0;
            cp16(dst, bp + (size_t)(r0 + row) * 2048 + kc2 + ck * 4);
        }
    };

    const int q = lane >> 3;
    const int wi = lane & 7;
    const int arow_base = wm * 32 + wi + ((q & 1) ? 8 : 0);
    const int akb_off = (q & 2) ? 16 : 0;
    const int brow_base = wn * 64 + wi + ((q & 2) ? 8 : 0);
    const int bkb_off = (q & 1) ? 16 : 0;

    load_stage(0, 0); CP_COMMIT;
    load_stage(1, 1); CP_COMMIT;

    for (int ch = 0; ch < 128; ++ch) {
        if (ch < 127) CP_WAIT(1); else CP_WAIT(0);
        __syncthreads();
        if (ch + 2 < 128) { load_stage(ch + 2, (ch + 2) % 3); CP_COMMIT; }

        const uint32_t sbase = smb + (uint32_t)(ch % 3) * 16384u;
        const uint32_t pAf = sbase, pBf = sbase + 8192u;

#pragma unroll
        for (int ks = 0; ks < 2; ++ks) {
            const int kb0 = ks * 32;
            uint32_t af[2][4];
#pragma unroll
            for (int mt = 0; mt < 2; ++mt) {
                const int r = arow_base + mt * 16;
                const uint32_t off = SWZ64(r * 64 + kb0 + akb_off);
                ldsm_x4(af[mt][0], af[mt][1], af[mt][2], af[mt][3], pAf + off);
            }
#pragma unroll
            for (int np = 0; np < 4; ++np) {
                const int rn = brow_base + np * 16;
                const uint32_t offb = SWZ64(rn * 64 + kb0 + bkb_off);
                uint32_t bf[4];
                ldsm_x4(bf[0], bf[1], bf[2], bf[3], pBf + offb);
#pragma unroll
                for (int mt = 0; mt < 2; ++mt) {
                    mma_f16(acc[mt][np * 2],     af[mt], bf[0], bf[1]);
                    mma_f16(acc[mt][np * 2 + 1], af[mt], bf[2], bf[3]);
                }
            }
        }
    }

    const int rl = lane >> 2;
    const int cl = (lane & 3) * 2;
#pragma unroll
    for (int mt = 0; mt < 2; ++mt) {
#pragma unroll
        for (int nn = 0; nn < 8; ++nn) {
            const int r = m0 + wm * 32 + mt * 16 + rl;
            const int c = n0 + wn * 64 + nn * 8 + cl;
#pragma unroll
            for (int half = 0; half < 2; ++half) {
                const int rr = r + half * 8;
                const float v0 = acc[mt][nn][half * 2];
                const float v1 = acc[mt][nn][half * 2 + 1];
                if (EPI == 0) {
                    *(float2*)&C[(size_t)rr * DMODEL + c] = make_float2(v0, v1);
                } else {
                    const int b = rr >> 11;
                    const int s = rr & (SEQ - 1);
                    const int h = c >> 7;
                    const int d = c & (HEADD - 1);
                    float2 f = *(const float2*)&freqs[(size_t)s * 64 + (d & 63)];
                    const size_t idx = (((size_t)b * NHEADS + h) * SEQ + s) * 64 + (d >> 1);
                    Qf[idx] = pack_f16(v0 * f.x * QSC2, v1 * f.y * QSC2);
                }
            }
        }
    }
}

// ---------------------------------------------------------------------------
// Tensor-core flash attention (causal), pure fp16 single-pass S and PV.
// Base-2 softmax. CTA: 64 q-rows, 4 warps, KV blocks of 32.
// Stages 3 x 16KB (Kf 8K | Vf 8K) + Q 16KB. 2 CTAs/SM.
// ---------------------------------------------------------------------------
#define ATT_QOFF 49152u
#define ATT_SMEM (49152 + 16384)

__global__ __launch_bounds__(128, 2) void attn_tc(
    const uint32_t* __restrict__ Qf,
    const uint32_t* __restrict__ Kf,
    const uint32_t* __restrict__ Vf,
    uint32_t* __restrict__ Of)
{
    extern __shared__ char sm[];
    const uint32_t smb = smem_to_u32(sm);
    const int tid = threadIdx.x;
    const int w = tid >> 5;
    const int lane = tid & 31;
    const int bx = gridDim.x - 1 - blockIdx.x;   // big tiles first
    const int by = blockIdx.y;
    const int b = by >> 5, h = by & 31, g = h >> 2;
    const int q0 = bx * 64;
    const int nb = 2 * bx + 2;                   // KV blocks of 32 rows

    // --- Q load (64 rows x 1 plane = 16KB) ---
    const size_t qbase = (((size_t)b * NHEADS + h) * SEQ + q0) * 64;
#pragma unroll
    for (int t = tid; t < 1024; t += 128) {
        const int row = t >> 4, ck = t & 15;
        const uint32_t dst = smb + ATT_QOFF + SWZ256(row * 256 + ck * 16);
        cp16(dst, Qf + qbase + (size_t)row * 64 + ck * 4);
    }
    CP_COMMIT;

    const size_t kvbase = ((size_t)b * NKVH + g) * KVLEN * 64;
    auto load_kv = [&](int jb, int region) {
        const uint32_t sb = smb + (uint32_t)region * 16384u;
        const int kv0 = jb * 32;
#pragma unroll
        for (int t = tid; t < 1024; t += 128) {
            const int plane = t >> 9;                 // Kf Vf
            const int i = t & 511;
            const int row = i >> 4, ck = i & 15;
            const uint32_t dst = sb + plane * 8192u + SWZ256(row * 256 + ck * 16);
            const uint32_t* base = plane ? Vf : Kf;
            cp16(dst, base + kvbase + (size_t)(kv0 + row) * 64 + ck * 4);
        }
    };

    load_kv(0, 0); CP_COMMIT;
    load_kv(1, 1); CP_COMMIT;
    CP_WAIT(2);                 // Q done
    __syncthreads();

    // --- preload Q fragments ---
    const int wi = lane & 7, qq = lane >> 3;
    const int arow = w * 16 + wi + ((qq & 1) ? 8 : 0);
    const int akoff = (qq & 2) ? 16 : 0;
    uint32_t qf[8][4];
#pragma unroll
    for (int ks = 0; ks < 8; ks++) {
        const uint32_t off = SWZ256(arow * 256 + ks * 32 + akoff);
        ldsm_x4(qf[ks][0], qf[ks][1], qf[ks][2], qf[ks][3], smb + ATT_QOFF + off);
    }

    float oacc[16][4];
#pragma unroll
    for (int i = 0; i < 16; i++)
#pragma unroll
        for (int v = 0; v < 4; v++) oacc[i][v] = 0.0f;
    float mprev0 = -INFINITY, mprev1 = -INFINITY;
    float lsum0 = 0.0f, lsum1 = 0.0f;

    const int rl = lane >> 2, cl2 = (lane & 3) * 2;
    const int row0g = q0 + w * 16 + rl;
    const int row1g = row0g + 8;
    const int brow = wi + ((qq & 2) ? 8 : 0);
    const int bkoff = (qq & 1) ? 16 : 0;
    const int vkr = (lane & 7) + ((lane & 8) ? 8 : 0);
    const int vnoff = (lane & 16) ? 16 : 0;

    for (int jb = 0; jb < nb; ++jb) {
        if (jb < nb - 1) CP_WAIT(1); else CP_WAIT(0);
        __syncthreads();
        if (jb + 2 < nb) { load_kv(jb + 2, (jb + 2) % 3); CP_COMMIT; }
        const uint32_t sb = smb + (uint32_t)(jb % 3) * 16384u;

        // --- S = Qf @ Kf^T (single-pass fp16), log2 domain ---
        float sacc[4][4];
#pragma unroll
        for (int i = 0; i < 4; i++)
#pragma unroll
            for (int v = 0; v < 4; v++) sacc[i][v] = 0.0f;
#pragma unroll
        for (int ks = 0; ks < 8; ks++) {
#pragma unroll
            for (int nt2 = 0; nt2 < 2; nt2++) {
                const uint32_t off = SWZ256((nt2 * 16 + brow) * 256 + ks * 32 + bkoff);
                uint32_t bf[4];
                ldsm_x4(bf[0], bf[1], bf[2], bf[3], sb + off);
                mma_f16(sacc[nt2 * 2],     qf[ks], bf[0], bf[1]);
                mma_f16(sacc[nt2 * 2 + 1], qf[ks], bf[2], bf[3]);
            }
        }

        // --- causal mask ---
        if (jb >= 2 * bx) {
            const int kv0 = jb * 32;
#pragma unroll
            for (int nt = 0; nt < 4; nt++) {
                const int c0 = kv0 + nt * 8 + cl2;
                const int c1 = c0 + 1;
                if (c0 > row0g) sacc[nt][0] = -1e30f;
                if (c1 > row0g) sacc[nt][1] = -1e30f;
                if (c0 > row1g) sacc[nt][2] = -1e30f;
                if (c1 > row1g) sacc[nt][3] = -1e30f;
            }
        }

        // --- online softmax (base 2) ---
        float mx0 = -1e30f, mx1 = -1e30f;
#pragma unroll
        for (int nt = 0; nt < 4; nt++) {
            mx0 = fmaxf(mx0, fmaxf(sacc[nt][0], sacc[nt][1]));
            mx1 = fmaxf(mx1, fmaxf(sacc[nt][2], sacc[nt][3]));
        }
        mx0 = fmaxf(mx0, __shfl_xor_sync(0xffffffffu, mx0, 1));
        mx0 = fmaxf(mx0, __shfl_xor_sync(0xffffffffu, mx0, 2));
        mx1 = fmaxf(mx1, __shfl_xor_sync(0xffffffffu, mx1, 1));
        mx1 = fmaxf(mx1, __shfl_xor_sync(0xffffffffu, mx1, 2));
        const float mnew0 = fmaxf(mprev0, mx0);
        const float mnew1 = fmaxf(mprev1, mx1);
        const float alpha0 = exp2f(mprev0 - mnew0);
        const float alpha1 = exp2f(mprev1 - mnew1);
        float rs0 = 0.0f, rs1 = 0.0f;
#pragma unroll
        for (int nt = 0; nt < 4; nt++) {
            sacc[nt][0] = exp2f(sacc[nt][0] - mnew0);
            sacc[nt][1] = exp2f(sacc[nt][1] - mnew0);
            sacc[nt][2] = exp2f(sacc[nt][2] - mnew1);
            sacc[nt][3] = exp2f(sacc[nt][3] - mnew1);
            rs0 += sacc[nt][0] + sacc[nt][1];
            rs1 += sacc[nt][2] + sacc[nt][3];
        }
        rs0 += __shfl_xor_sync(0xffffffffu, rs0, 1);
        rs0 += __shfl_xor_sync(0xffffffffu, rs0, 2);
        rs1 += __shfl_xor_sync(0xffffffffu, rs1, 1);
        rs1 += __shfl_xor_sync(0xffffffffu, rs1, 2);
        lsum0 = lsum0 * alpha0 + rs0;
        lsum1 = lsum1 * alpha1 + rs1;
#pragma unroll
        for (int nt = 0; nt < 16; nt++) {
            oacc[nt][0] *= alpha0; oacc[nt][1] *= alpha0;
            oacc[nt][2] *= alpha1; oacc[nt][3] *= alpha1;
        }
        mprev0 = mnew0; mprev1 = mnew1;

        // --- O += P @ V (single-pass fp16) ---
#pragma unroll
        for (int jp = 0; jp < 2; jp++) {
            uint32_t pf[4];
            pf[0] = pack_f16(sacc[2 * jp][0],     sacc[2 * jp][1]);
            pf[1] = pack_f16(sacc[2 * jp][2],     sacc[2 * jp][3]);
            pf[2] = pack_f16(sacc[2 * jp + 1][0], sacc[2 * jp + 1][1]);
            pf[3] = pack_f16(sacc[2 * jp + 1][2], sacc[2 * jp + 1][3]);
#pragma unroll
            for (int nt2 = 0; nt2 < 8; nt2++) {
                const uint32_t off = SWZ256((jp * 16 + vkr) * 256 + nt2 * 32 + vnoff);
                uint32_t vh[4];
                ldsm_x4_t(vh[0], vh[1], vh[2], vh[3], sb + 8192u + off);
                mma_f16(oacc[nt2 * 2],     pf, vh[0], vh[1]);
                mma_f16(oacc[nt2 * 2 + 1], pf, vh[2], vh[3]);
            }
        }
    }

    // --- epilogue: normalize, fp16 pack, single plane (b*s, h*d) ---
    const float inv0 = 1.0f / lsum0;
    const float inv1 = 1.0f / lsum1;
    const size_t r0 = ((size_t)b * SEQ + row0g) * 2048 + h * 64;
    const size_t r1 = ((size_t)b * SEQ + row1g) * 2048 + h * 64;
#pragma unroll
    for (int nt = 0; nt < 16; nt++) {
        const int d2 = (nt * 8 + cl2) >> 1;
        Of[r0 + d2] = pack_f16(oacc[nt][0] * inv0, oacc[nt][1] * inv0);
        Of[r1 + d2] = pack_f16(oacc[nt][2] * inv1, oacc[nt][3] * inv1);
    }
}

// ---------------------------------------------------------------------------
extern "C" void kernel_launch(void* const* d_in, const int* in_sizes, int n_in,
                              void* d_out, int out_size)
{
    (void)in_sizes; (void)n_in; (void)out_size;
    const float* x     = (const float*)d_in[0];
    const float* freqs = (const float*)d_in[1];
    const float* wq    = (const float*)d_in[3];
    const float* wo    = (const float*)d_in[6];
    const float* ck    = (const float*)d_in[7];
    const float* cv    = (const float*)d_in[8];
    float* out = (float*)d_out;

    void *xf, *wqf, *wof, *qf, *af, *kf, *vf;
    cudaGetSymbolAddress(&xf, g_xf);
    cudaGetSymbolAddress(&wqf, g_wqf);
    cudaGetSymbolAddress(&wof, g_wof);
    cudaGetSymbolAddress(&qf, g_qf);
    cudaGetSymbolAddress(&af, g_af);
    cudaGetSymbolAddress(&kf, g_kf);
    cudaGetSymbolAddress(&vf, g_vf);

    cudaFuncSetAttribute(gemm_f16<0>, cudaFuncAttributeMaxDynamicSharedMemorySize, GEMM1_SMEM);
    cudaFuncSetAttribute(gemm_f16<1>, cudaFuncAttributeMaxDynamicSharedMemorySize, GEMM1_SMEM);
    cudaFuncSetAttribute(attn_tc, cudaFuncAttributeMaxDynamicSharedMemorySize, ATT_SMEM);

    dim3 blk(256);
    conv3<<<dim3(2048, 3), blk>>>(
        (const float4*)x, (const float4*)wq, (const float4*)wo,
        (uint2*)xf, (uint2*)wqf, (uint2*)wof);
    conv_kv4<<<dim3(1024, 2), blk>>>(
        (const float4*)ck, (const float4*)cv,
        (uint2*)kf, (uint2*)vf);

    gemm_f16<1><<<dim3(32, 32), blk, GEMM1_SMEM>>>(
        (const uint32_t*)xf, (const uint32_t*)wqf,
        nullptr, freqs, (uint32_t*)qf);

    attn_tc<<<dim3(32, 64), dim3(128), ATT_SMEM>>>(
        (const uint32_t*)qf,
        (const uint32_t*)kf,
        (const uint32_t*)vf,
        (uint32_t*)af);

    gemm_f16<0><<<dim3(32, 32), blk, GEMM1_SMEM>>>(
        (const uint32_t*)af, (const uint32_t*)wof,
        out, nullptr, nullptr);
}